// round 11
// baseline (speedup 1.0000x reference)
#include <cuda_runtime.h>
#include <cstdint>

// Problem constants (fixed by dataset)
#define BB 64
#define TT 128
#define SS 512
#define EE 1024
#define DD 512
#define NEGINF (-1.0e10f)
#define PAD 132
#define APITCH_F 20

// bf16 pipeline tile geometry: [128 rows][16 k] bf16, 48B pitch (32B data+16B pad)
#define BPITCH 48
#define BTILE  (128 * BPITCH)        // 6144 B
#define BSTG   (4 * BTILE)           // Ah, Al, Bh, Bl per stage = 24576 B
#define NST    4
#define SMEM_PIPE (NST * BSTG)       // 98304 B

// Scratch (allocation-free rule: device globals)
__device__ uint32_t g_Ph[(size_t)BB * TT * EE / 2];   // P hi (bf16x2)
__device__ uint32_t g_Pl[(size_t)BB * TT * EE / 2];   // P lo
__device__ uint32_t g_dech[(size_t)BB * TT * DD / 2], g_decl[(size_t)BB * TT * DD / 2];
__device__ uint32_t g_wah[(size_t)EE * DD / 2],       g_wal[(size_t)EE * DD / 2];
__device__ uint32_t g_ench[(size_t)BB * SS * EE / 2], g_encl[(size_t)BB * SS * EE / 2];
__device__ float g_wc[(size_t)BB * TT * EE];
__device__ float g_c[(size_t)BB * TT];
__device__ float g_attn_scratch[(size_t)BB * TT * SS];
__device__ float g_me_scratch[(size_t)BB * TT * SS];

// ---------------------------------------------------------------------------
// helpers
// ---------------------------------------------------------------------------
__device__ __forceinline__ uint32_t smem_u32(const void* p) {
    uint32_t a;
    asm("{ .reg .u64 t; cvta.to.shared.u64 t, %1; cvt.u32.u64 %0, t; }"
        : "=r"(a) : "l"(p));
    return a;
}

__device__ __forceinline__ float f2tf32(float x) {
    uint32_t u;
    asm("cvt.rna.tf32.f32 %0, %1;" : "=r"(u) : "f"(x));
    return __uint_as_float(u);
}

__device__ __forceinline__ void cpa16(uint32_t s, const void* g) {
    asm volatile("cp.async.cg.shared.global [%0], [%1], 16;"
                 :: "r"(s), "l"(g) : "memory");
}
#define CP_COMMIT() asm volatile("cp.async.commit_group;" ::: "memory")

#define LDSM4(d0, d1, d2, d3, a)                                              \
    asm volatile("ldmatrix.sync.aligned.m8n8.x4.shared.b16 {%0,%1,%2,%3}, [%4];" \
                 : "=r"(d0), "=r"(d1), "=r"(d2), "=r"(d3) : "r"(a))

__device__ __forceinline__ void mma8u(float* d, const uint32_t* a, const float* b) {
    asm volatile(
        "mma.sync.aligned.m16n8k8.row.col.f32.tf32.tf32.f32 "
        "{%0,%1,%2,%3}, {%4,%5,%6,%7}, {%8,%9}, {%0,%1,%2,%3};"
        : "+f"(d[0]), "+f"(d[1]), "+f"(d[2]), "+f"(d[3])
        : "r"(a[0]), "r"(a[1]), "r"(a[2]), "r"(a[3]),
          "r"(__float_as_uint(b[0])), "r"(__float_as_uint(b[1])));
}

__device__ __forceinline__ void mma16(float* d, const uint32_t* a, const uint32_t* b) {
    asm volatile(
        "mma.sync.aligned.m16n8k16.row.col.f32.bf16.bf16.f32 "
        "{%0,%1,%2,%3}, {%4,%5,%6,%7}, {%8,%9}, {%0,%1,%2,%3};"
        : "+f"(d[0]), "+f"(d[1]), "+f"(d[2]), "+f"(d[3])
        : "r"(a[0]), "r"(a[1]), "r"(a[2]), "r"(a[3]), "r"(b[0]), "r"(b[1]));
}

// pack two fp32 into bf16x2 hi + residual lo
__device__ __forceinline__ void split2(float x, float y, uint32_t& h, uint32_t& l) {
    asm("cvt.rn.satfinite.bf16x2.f32 %0, %1, %2;" : "=r"(h) : "f"(y), "f"(x));
    const float hx = __uint_as_float(h << 16);
    const float hy = __uint_as_float(h & 0xFFFF0000u);
    asm("cvt.rn.satfinite.bf16x2.f32 %0, %1, %2;" : "=r"(l) : "f"(y - hy), "f"(x - hx));
}

// One K16 chunk of bf16 2-term split via ldmatrix. Bases are u32 smem addrs.
#define COMPUTE_BF_LDSM(AHB, ALB, BHB, BLB) do {                              \
    uint32_t ah[4][4], al[4][4], bh[4][2], bl[4][2];                          \
    _Pragma("unroll")                                                         \
    for (int mi = 0; mi < 4; mi++) {                                          \
        const uint32_t _ao = aoff + mi * (16 * BPITCH);                       \
        LDSM4(ah[mi][0], ah[mi][1], ah[mi][2], ah[mi][3], (AHB) + _ao);       \
        LDSM4(al[mi][0], al[mi][1], al[mi][2], al[mi][3], (ALB) + _ao);       \
    }                                                                         \
    _Pragma("unroll")                                                         \
    for (int p = 0; p < 2; p++) {                                             \
        const uint32_t _bo = boff + p * (16 * BPITCH);                        \
        LDSM4(bh[2*p][0], bh[2*p][1], bh[2*p+1][0], bh[2*p+1][1], (BHB) + _bo); \
        LDSM4(bl[2*p][0], bl[2*p][1], bl[2*p+1][0], bl[2*p+1][1], (BLB) + _bo); \
    }                                                                         \
    _Pragma("unroll")                                                         \
    for (int mi = 0; mi < 4; mi++)                                            \
        _Pragma("unroll")                                                     \
        for (int nj = 0; nj < 4; nj++) {                                      \
            mma16(acc[mi][nj], ah[mi], bh[nj]);                               \
            mma16(acc[mi][nj], ah[mi], bl[nj]);                               \
            mma16(acc[mi][nj], al[mi], bh[nj]);                               \
        }                                                                     \
} while (0)

// ---------------------------------------------------------------------------
// tf32 staging/compute (k_wc / k_out) — unchanged from R9
// ---------------------------------------------------------------------------
#define STAGE_A32(dst, v, p) do {                                             \
    const int _r = lrow + (p) * 64;                                           \
    float4 _cv;                                                               \
    _cv.x = f2tf32((v).x); _cv.y = f2tf32((v).y);                             \
    _cv.z = f2tf32((v).z); _cv.w = f2tf32((v).w);                             \
    *(float4*)&(dst)[_r * APITCH_F + (tid & 3) * 4] = _cv;                    \
} while (0)

#define STAGE_D(H, v, p) do {                                   \
    float4 _cv;                                                 \
    _cv.x = f2tf32((v).x); _cv.y = f2tf32((v).y);               \
    _cv.z = f2tf32((v).z); _cv.w = f2tf32((v).w);               \
    *(float4*)&H[krow + (p) * 8][ncol] = _cv;                   \
} while (0)

#define COMPUTE_T32_LDSM(A32B, Bhb)                                           \
    _Pragma("unroll")                                                         \
    for (int ks = 0; ks < 2; ks++) {                                          \
        const int k0 = ks * 8;                                                \
        uint32_t au[4][4];                                                    \
        float bf[4][2];                                                       \
        _Pragma("unroll")                                                     \
        for (int mi = 0; mi < 4; mi++) {                                      \
            const uint32_t _ao = aoff32 + mi * (16 * 80) + ks * 32;           \
            LDSM4(au[mi][0], au[mi][1], au[mi][2], au[mi][3], (A32B) + _ao);  \
        }                                                                     \
        _Pragma("unroll")                                                     \
        for (int nj = 0; nj < 4; nj++) {                                      \
            const int n = bn0 + nj * 8 + qr;                                  \
            bf[nj][0] = Bhb[k0 + qc][n]; bf[nj][1] = Bhb[k0 + qc + 4][n];     \
        }                                                                     \
        _Pragma("unroll")                                                     \
        for (int mi = 0; mi < 4; mi++)                                        \
            _Pragma("unroll")                                                 \
            for (int nj = 0; nj < 4; nj++)                                    \
                mma8u(acc[mi][nj], au[mi], bf[nj]);                           \
    }

#define WARP_IDX_SETUP                                  \
    const int tid = threadIdx.x;                        \
    const int lane = tid & 31, wid = tid >> 5;          \
    const int qr = lane >> 2, qc = lane & 3;            \
    const int am0 = (wid >> 2) * 64;                    \
    const int bn0 = (wid & 3) * 32;                     \
    const int lrow = tid >> 2, lcol = (tid & 3) * 4;    \
    const int krow = tid >> 5, ncol = (tid & 31) * 4;   \
    (void)qr; (void)qc; (void)krow; (void)ncol; (void)lcol;

#define LDSM_A_IDX                                                            \
    const int a_row = ((lane >> 3) & 1) * 8 + (lane & 7);                     \
    const int a_kh  = ((lane >> 4) & 1) * 16;
#define LDSM_B_IDX                                                            \
    const int b_row = ((lane >> 4) & 1) * 8 + (lane & 7);                     \
    const int b_kh  = ((lane >> 3) & 1) * 16;

// ---------------------------------------------------------------------------
// prep: fp32 -> bf16 hi/lo split (grid-stride over float4)
// ---------------------------------------------------------------------------
__global__ __launch_bounds__(256)
void k_split(const float4* __restrict__ in, uint2* __restrict__ hi,
             uint2* __restrict__ lo, int n4)
{
    const int i = blockIdx.x * 256 + threadIdx.x;
    if (i >= n4) return;
    const float4 v = in[i];
    uint32_t h0, h1, l0, l1;
    split2(v.x, v.y, h0, l0);
    split2(v.z, v.w, h1, l1);
    hi[i] = make_uint2(h0, h1);
    lo[i] = make_uint2(l0, l1);
}

// Kernel c: c[m] = sum_d dec[m,d] * b_attn[d]
__global__ __launch_bounds__(256)
void k_c(const float* __restrict__ dec, const float* __restrict__ ba)
{
    const int m = blockIdx.x * 8 + (threadIdx.x >> 5);
    const int lane = threadIdx.x & 31;
    float s = 0.0f;
#pragma unroll
    for (int it = 0; it < 4; it++) {
        float4 v = *(const float4*)&dec[(size_t)m * DD + it * 128 + lane * 4];
        float4 w = *(const float4*)&ba[it * 128 + lane * 4];
        s += v.x * w.x + v.y * w.y + v.z * w.z + v.w * w.w;
    }
#pragma unroll
    for (int o = 16; o; o >>= 1) s += __shfl_xor_sync(0xffffffffu, s, o);
    if (lane == 0) g_c[m] = s;
}

// ---------------------------------------------------------------------------
// k_P (cp.async 4-stage, bf16-split): P[m,e] = sum_d dec[m,d]*W[e,d]
// A rows from g_dech/g_decl (stride 1024B), B rows g_wah/g_wal (1024B).
// Epilogue writes P as bf16 hi/lo.
// ---------------------------------------------------------------------------
__global__ __launch_bounds__(256)
void k_P(const char* __restrict__ ahg, const char* __restrict__ alg,
         const char* __restrict__ bhg, const char* __restrict__ blg,
         uint32_t* __restrict__ Ph, uint32_t* __restrict__ Pl)
{
    extern __shared__ char smx[];
    WARP_IDX_SETUP
    LDSM_A_IDX
    LDSM_B_IDX
    const int bm = blockIdx.y * 128, bn = blockIdx.x * 128;
    const uint32_t sb = smem_u32(smx);
    const uint32_t aoff = (am0 + a_row) * BPITCH + a_kh;
    const uint32_t boff = (bn0 + b_row) * BPITCH + b_kh;

    const int srow = tid >> 1, sseg = tid & 1;
    const uint32_t s_off = srow * BPITCH + sseg * 16;
    const char* ga[4] = {
        ahg + (size_t)(bm + srow) * (DD * 2) + sseg * 16,
        alg + (size_t)(bm + srow) * (DD * 2) + sseg * 16,
        bhg + (size_t)(bn + srow) * (DD * 2) + sseg * 16,
        blg + (size_t)(bn + srow) * (DD * 2) + sseg * 16 };

    const int nst = DD / 16;  // 32
#pragma unroll
    for (int s = 0; s < NST - 1; s++) {
        const uint32_t st = sb + s * BSTG + s_off;
#pragma unroll
        for (int tl = 0; tl < 4; tl++) cpa16(st + tl * BTILE, ga[tl] + s * 32);
        CP_COMMIT();
    }

    float acc[4][4][4] = {};
    for (int t = 0; t < nst; t++) {
        asm volatile("cp.async.wait_group %0;" :: "n"(NST - 2) : "memory");
        __syncthreads();
        const int tn = t + NST - 1;
        if (tn < nst) {
            const uint32_t st = sb + (tn % NST) * BSTG + s_off;
#pragma unroll
            for (int tl = 0; tl < 4; tl++)
                cpa16(st + tl * BTILE, ga[tl] + (size_t)tn * 32);
        }
        CP_COMMIT();
        const uint32_t s0 = sb + (t % NST) * BSTG;
        COMPUTE_BF_LDSM(s0, s0 + BTILE, s0 + 2 * BTILE, s0 + 3 * BTILE);
    }
#pragma unroll
    for (int mi = 0; mi < 4; mi++)
#pragma unroll
        for (int nj = 0; nj < 4; nj++) {
            const size_t m = bm + am0 + mi * 16 + qr;
            const int n = bn + bn0 + nj * 8 + qc * 2;
            uint32_t h, l;
            split2(acc[mi][nj][0], acc[mi][nj][1], h, l);
            Ph[(m * EE + n) >> 1] = h; Pl[(m * EE + n) >> 1] = l;
            split2(acc[mi][nj][2], acc[mi][nj][3], h, l);
            Ph[((m + 8) * EE + n) >> 1] = h; Pl[((m + 8) * EE + n) >> 1] = l;
        }
}

// ---------------------------------------------------------------------------
// k_energy (cp.async 4-stage, bf16-split, per batch):
// me[t,s] = mask[s] ? P[t,:].enc[s,:] + c[t] : NEGINF.  K=1024 (64 stages)
// ---------------------------------------------------------------------------
__global__ __launch_bounds__(256)
void k_energy(const char* __restrict__ phg, const char* __restrict__ plg,
              const char* __restrict__ ehg, const char* __restrict__ elg,
              const int* __restrict__ mask, float* __restrict__ me)
{
    extern __shared__ char smx[];
    WARP_IDX_SETUP
    LDSM_A_IDX
    LDSM_B_IDX
    const int b = blockIdx.z;
    const int bn = blockIdx.x * 128;
    const uint32_t sb = smem_u32(smx);
    const uint32_t aoff = (am0 + a_row) * BPITCH + a_kh;
    const uint32_t boff = (bn0 + b_row) * BPITCH + b_kh;

    const int srow = tid >> 1, sseg = tid & 1;
    const uint32_t s_off = srow * BPITCH + sseg * 16;
    const char* ga[4] = {
        phg + ((size_t)b * TT + srow) * (EE * 2) + sseg * 16,
        plg + ((size_t)b * TT + srow) * (EE * 2) + sseg * 16,
        ehg + ((size_t)b * SS + bn + srow) * (EE * 2) + sseg * 16,
        elg + ((size_t)b * SS + bn + srow) * (EE * 2) + sseg * 16 };

    const int nst = EE / 16;  // 64
#pragma unroll
    for (int s = 0; s < NST - 1; s++) {
        const uint32_t st = sb + s * BSTG + s_off;
#pragma unroll
        for (int tl = 0; tl < 4; tl++) cpa16(st + tl * BTILE, ga[tl] + s * 32);
        CP_COMMIT();
    }

    float acc[4][4][4] = {};
    for (int t = 0; t < nst; t++) {
        asm volatile("cp.async.wait_group %0;" :: "n"(NST - 2) : "memory");
        __syncthreads();
        const int tn = t + NST - 1;
        if (tn < nst) {
            const uint32_t st = sb + (tn % NST) * BSTG + s_off;
#pragma unroll
            for (int tl = 0; tl < 4; tl++)
                cpa16(st + tl * BTILE, ga[tl] + (size_t)tn * 32);
        }
        CP_COMMIT();
        const uint32_t s0 = sb + (t % NST) * BSTG;
        COMPUTE_BF_LDSM(s0, s0 + BTILE, s0 + 2 * BTILE, s0 + 3 * BTILE);
    }
#pragma unroll
    for (int mi = 0; mi < 4; mi++) {
        const int t0 = am0 + mi * 16 + qr;
        const float ct0 = g_c[(size_t)b * TT + t0];
        const float ct1 = g_c[(size_t)b * TT + t0 + 8];
#pragma unroll
        for (int nj = 0; nj < 4; nj++) {
            const int s = bn + bn0 + nj * 8 + qc * 2;
            const int mk0 = mask[(size_t)b * SS + s];
            const int mk1 = mask[(size_t)b * SS + s + 1];
            float2 r0, r1;
            r0.x = mk0 ? acc[mi][nj][0] + ct0 : NEGINF;
            r0.y = mk1 ? acc[mi][nj][1] + ct0 : NEGINF;
            r1.x = mk0 ? acc[mi][nj][2] + ct1 : NEGINF;
            r1.y = mk1 ? acc[mi][nj][3] + ct1 : NEGINF;
            *(float2*)&me[((size_t)b * TT + t0) * SS + s]     = r0;
            *(float2*)&me[((size_t)b * TT + t0 + 8) * SS + s] = r1;
        }
    }
}

// Row softmax over S=512, one block (256 thr) per (b,t) row.
__global__ __launch_bounds__(256)
void k_softmax(const float* __restrict__ me, float* __restrict__ attn)
{
    const int row = blockIdx.x;
    const float* x = me + (size_t)row * SS;
    float* y = attn + (size_t)row * SS;
    const int tid = threadIdx.x;
    __shared__ float smax[8];
    __shared__ float ssum[8];

    float v0 = x[tid], v1 = x[tid + 256];
    float m = fmaxf(v0, v1);
#pragma unroll
    for (int o = 16; o; o >>= 1) m = fmaxf(m, __shfl_xor_sync(0xffffffffu, m, o));
    if ((tid & 31) == 0) smax[tid >> 5] = m;
    __syncthreads();
    float M = smax[0];
#pragma unroll
    for (int i = 1; i < 8; i++) M = fmaxf(M, smax[i]);

    float e0 = __expf(v0 - M), e1 = __expf(v1 - M);
    float s = e0 + e1;
#pragma unroll
    for (int o = 16; o; o >>= 1) s += __shfl_xor_sync(0xffffffffu, s, o);
    if ((tid & 31) == 0) ssum[tid >> 5] = s;
    __syncthreads();
    float S = 0.0f;
#pragma unroll
    for (int i = 0; i < 8; i++) S += ssum[i];
    float inv = 1.0f / S;
    y[tid] = e0 * inv;
    y[tid + 256] = e1 * inv;
}

// k_wc (tf32 + A-ldmatrix, per batch): wc[t,e] = sum_s attn[t,s]*enc[s,e]
__global__ __launch_bounds__(256)
void k_wc(const float* __restrict__ attn, const float* __restrict__ enc)
{
    __shared__ float A32[2][128 * APITCH_F];
    __shared__ float Bh[2][16][PAD];
    WARP_IDX_SETUP
    LDSM_A_IDX
    const int b = blockIdx.z;
    const int bn = blockIdx.x * 128;
    const float* A = attn + (size_t)b * TT * SS;
    const float* Ep = enc + (size_t)b * SS * EE;
    const uint32_t a32b[2] = { smem_u32(A32[0]), smem_u32(A32[1]) };
    const uint32_t aoff32 = (am0 + a_row) * 80 + a_kh;

    float4 va[2], vb[2];
#pragma unroll
    for (int p = 0; p < 2; p++) {
        va[p] = *(const float4*)&A[(size_t)(lrow + p * 64) * SS + lcol];
        vb[p] = *(const float4*)&Ep[(size_t)(krow + p * 8) * EE + bn + ncol];
    }
    STAGE_A32(A32[0], va[0], 0); STAGE_A32(A32[0], va[1], 1);
    STAGE_D(Bh[0], vb[0], 0); STAGE_D(Bh[0], vb[1], 1);
    __syncthreads();

    float acc[4][4][4] = {};
    const int nt = SS / 16;
    for (int t = 0; t < nt; t++) {
        const int cur = t & 1, nxt = cur ^ 1;
        const bool more = (t + 1 < nt);
        if (more) {
            const int k0 = (t + 1) * 16;
#pragma unroll
            for (int p = 0; p < 2; p++) {
                va[p] = *(const float4*)&A[(size_t)(lrow + p * 64) * SS + k0 + lcol];
                vb[p] = *(const float4*)&Ep[(size_t)(k0 + krow + p * 8) * EE + bn + ncol];
            }
        }
        COMPUTE_T32_LDSM(a32b[cur], Bh[cur])
        if (more) {
            STAGE_A32(A32[nxt], va[0], 0); STAGE_A32(A32[nxt], va[1], 1);
            STAGE_D(Bh[nxt], vb[0], 0); STAGE_D(Bh[nxt], vb[1], 1);
        }
        __syncthreads();
    }
#pragma unroll
    for (int mi = 0; mi < 4; mi++)
#pragma unroll
        for (int nj = 0; nj < 4; nj++) {
            const size_t m = (size_t)b * TT + am0 + mi * 16 + qr;
            const int n = bn + bn0 + nj * 8 + qc * 2;
            *(float2*)&g_wc[m * EE + n]       = make_float2(acc[mi][nj][0], acc[mi][nj][1]);
            *(float2*)&g_wc[(m + 8) * EE + n] = make_float2(acc[mi][nj][2], acc[mi][nj][3]);
        }
}

// k_out (tf32 + A-ldmatrix): ht[m,n] = tanh([wc | dec][m,:] @ W_out[:,n])
__global__ __launch_bounds__(256)
void k_out(const float* __restrict__ dec, const float* __restrict__ Wout,
           float* __restrict__ ht)
{
    __shared__ float A32[2][128 * APITCH_F];
    __shared__ float Bh[2][16][PAD];
    WARP_IDX_SETUP
    LDSM_A_IDX
    const int bm = blockIdx.y * 128, bn = blockIdx.x * 128;
    const uint32_t a32b[2] = { smem_u32(A32[0]), smem_u32(A32[1]) };
    const uint32_t aoff32 = (am0 + a_row) * 80 + a_kh;

    float4 va[2], vb[2];
#pragma unroll
    for (int p = 0; p < 2; p++) {
        va[p] = *(const float4*)&g_wc[(size_t)(bm + lrow + p * 64) * EE + lcol];
        vb[p] = *(const float4*)&Wout[(size_t)(krow + p * 8) * DD + bn + ncol];
    }
    STAGE_A32(A32[0], va[0], 0); STAGE_A32(A32[0], va[1], 1);
    STAGE_D(Bh[0], vb[0], 0); STAGE_D(Bh[0], vb[1], 1);
    __syncthreads();

    float acc[4][4][4] = {};
    const int nt = (EE + DD) / 16;
    for (int t = 0; t < nt; t++) {
        const int cur = t & 1, nxt = cur ^ 1;
        const bool more = (t + 1 < nt);
        if (more) {
            const int k0 = (t + 1) * 16;
#pragma unroll
            for (int p = 0; p < 2; p++) {
                if (k0 < EE)
                    va[p] = *(const float4*)&g_wc[(size_t)(bm + lrow + p * 64) * EE + k0 + lcol];
                else
                    va[p] = *(const float4*)&dec[(size_t)(bm + lrow + p * 64) * DD + (k0 - EE) + lcol];
                vb[p] = *(const float4*)&Wout[(size_t)(k0 + krow + p * 8) * DD + bn + ncol];
            }
        }
        COMPUTE_T32_LDSM(a32b[cur], Bh[cur])
        if (more) {
            STAGE_A32(A32[nxt], va[0], 0); STAGE_A32(A32[nxt], va[1], 1);
            STAGE_D(Bh[nxt], vb[0], 0); STAGE_D(Bh[nxt], vb[1], 1);
        }
        __syncthreads();
    }
#pragma unroll
    for (int mi = 0; mi < 4; mi++)
#pragma unroll
        for (int nj = 0; nj < 4; nj++) {
            const size_t m = bm + am0 + mi * 16 + qr;
            const int n = bn + bn0 + nj * 8 + qc * 2;
            float2 r0 = make_float2(tanhf(acc[mi][nj][0]), tanhf(acc[mi][nj][1]));
            float2 r1 = make_float2(tanhf(acc[mi][nj][2]), tanhf(acc[mi][nj][3]));
            *(float2*)&ht[m * DD + n]       = r0;
            *(float2*)&ht[(m + 8) * DD + n] = r1;
        }
}

extern "C" void kernel_launch(void* const* d_in, const int* in_sizes, int n_in,
                              void* d_out, int out_size)
{
    const float* dec    = (const float*)d_in[0];
    const float* enc    = (const float*)d_in[1];
    const int*   mask   = (const int*)d_in[2];
    const float* W_attn = (const float*)d_in[3];
    const float* b_attn = (const float*)d_in[4];
    const float* W_out  = (const float*)d_in[5];
    float* out = (float*)d_out;

    const size_t n_h    = (size_t)BB * TT * DD;
    const size_t n_attn = (size_t)BB * TT * SS;
    const size_t n_me   = (size_t)BB * TT * SS;

    float* h_tilde = out;
    float* attn;
    float* me;
    if ((size_t)out_size >= n_h + n_attn + n_me) {
        attn = out + n_h;
        me   = out + n_h + n_attn;
    } else {
        void* p;
        cudaGetSymbolAddress(&p, g_attn_scratch); attn = (float*)p;
        cudaGetSymbolAddress(&p, g_me_scratch);   me = (float*)p;
    }

    void *p_dech, *p_decl, *p_wah, *p_wal, *p_ench, *p_encl, *p_Ph, *p_Pl;
    cudaGetSymbolAddress(&p_dech, g_dech); cudaGetSymbolAddress(&p_decl, g_decl);
    cudaGetSymbolAddress(&p_wah, g_wah);   cudaGetSymbolAddress(&p_wal, g_wal);
    cudaGetSymbolAddress(&p_ench, g_ench); cudaGetSymbolAddress(&p_encl, g_encl);
    cudaGetSymbolAddress(&p_Ph, g_Ph);     cudaGetSymbolAddress(&p_Pl, g_Pl);

    cudaFuncSetAttribute(k_P, cudaFuncAttributeMaxDynamicSharedMemorySize, SMEM_PIPE);
    cudaFuncSetAttribute(k_energy, cudaFuncAttributeMaxDynamicSharedMemorySize, SMEM_PIPE);

    // prep: bf16 hi/lo splits of dec, W_attn, enc
    const int n4_dec = BB * TT * DD / 4;
    const int n4_wa  = EE * DD / 4;
    const int n4_enc = BB * SS * EE / 4;
    k_split<<<(n4_dec + 255) / 256, 256>>>((const float4*)dec, (uint2*)p_dech, (uint2*)p_decl, n4_dec);
    k_split<<<(n4_wa  + 255) / 256, 256>>>((const float4*)W_attn, (uint2*)p_wah, (uint2*)p_wal, n4_wa);
    k_split<<<(n4_enc + 255) / 256, 256>>>((const float4*)enc, (uint2*)p_ench, (uint2*)p_encl, n4_enc);

    // 0. c = dec . b_attn
    k_c<<<dim3(BB * TT / 8), 256>>>(dec, b_attn);
    // 1. P = dec @ W_attn^T (bf16-split, cp.async pipeline)
    k_P<<<dim3(EE / 128, (BB * TT) / 128), 256, SMEM_PIPE>>>(
        (const char*)p_dech, (const char*)p_decl,
        (const char*)p_wah, (const char*)p_wal,
        (uint32_t*)p_Ph, (uint32_t*)p_Pl);
    // 2. masked energies (bf16-split, cp.async pipeline)  per-batch M=128 N=512 K=1024
    k_energy<<<dim3(SS / 128, 1, BB), 256, SMEM_PIPE>>>(
        (const char*)p_Ph, (const char*)p_Pl,
        (const char*)p_ench, (const char*)p_encl, mask, me);
    // 3. softmax rows
    k_softmax<<<dim3(BB * TT), 256>>>(me, attn);
    // 4. weighted context (tf32 + A-ldmatrix)  per-batch M=128 N=1024 K=512
    k_wc<<<dim3(EE / 128, 1, BB), 256>>>(attn, enc);
    // 5. h_tilde = tanh([wc, dec] @ W_out)     M=8192 K=1536 N=512
    k_out<<<dim3(DD / 128, (BB * TT) / 128), 256>>>(dec, W_out, h_tilde);
}

// round 12
// speedup vs baseline: 1.0382x; 1.0382x over previous
#include <cuda_runtime.h>
#include <cstdint>

// Problem constants (fixed by dataset)
#define BB 64
#define TT 128
#define SS 512
#define EE 1024
#define DD 512
#define NEGINF (-1.0e10f)
#define PAD 132
#define APITCH_F 20

// bf16 tile geometry (k_P / k_energy): [128 rows][16 k] bf16, 48B pitch
#define BPITCH 48
#define BTILE  (128 * BPITCH)      // 6144 B
#define BSTG   (4 * BTILE)         // Ah, Al, Bh, Bl per stage = 24576 B
#define SMEM_BF (2 * BSTG)         // 49152 B

// tf32 cp.async tile geometry (k_wc / k_out)
#define ASZ32  (128 * 80)          // A: 128 m-rows x (64B data + 16B pad) = 10240
#define BSZ32  (16 * (PAD * 4))    // B: 16 k-rows x 528B = 8448
#define STG32  (ASZ32 + BSZ32)     // 18688
#define NST    4
#define SMEM32 (NST * STG32)       // 74752

// Scratch (allocation-free rule: device globals)
__device__ float g_P[(size_t)BB * TT * EE];
__device__ float g_wc[(size_t)BB * TT * EE];
__device__ float g_c[(size_t)BB * TT];
__device__ float g_attn_scratch[(size_t)BB * TT * SS];
__device__ float g_me_scratch[(size_t)BB * TT * SS];

// ---------------------------------------------------------------------------
// helpers
// ---------------------------------------------------------------------------
__device__ __forceinline__ uint32_t smem_u32(const void* p) {
    uint32_t a;
    asm("{ .reg .u64 t; cvta.to.shared.u64 t, %1; cvt.u32.u64 %0, t; }"
        : "=r"(a) : "l"(p));
    return a;
}

__device__ __forceinline__ float f2tf32(float x) {
    uint32_t u;
    asm("cvt.rna.tf32.f32 %0, %1;" : "=r"(u) : "f"(x));
    return __uint_as_float(u);
}

__device__ __forceinline__ uint32_t tf32u(uint32_t raw) {
    uint32_t u;
    asm("cvt.rna.tf32.f32 %0, %1;" : "=r"(u) : "f"(__uint_as_float(raw)));
    return u;
}

__device__ __forceinline__ void cpa16(uint32_t s, const void* g) {
    asm volatile("cp.async.cg.shared.global [%0], [%1], 16;"
                 :: "r"(s), "l"(g) : "memory");
}
#define CP_COMMIT() asm volatile("cp.async.commit_group;" ::: "memory")

#define LDSM4(d0, d1, d2, d3, a)                                              \
    asm volatile("ldmatrix.sync.aligned.m8n8.x4.shared.b16 {%0,%1,%2,%3}, [%4];" \
                 : "=r"(d0), "=r"(d1), "=r"(d2), "=r"(d3) : "r"(a))

__device__ __forceinline__ void mma8u(float* d, const uint32_t* a, const float* b) {
    asm volatile(
        "mma.sync.aligned.m16n8k8.row.col.f32.tf32.tf32.f32 "
        "{%0,%1,%2,%3}, {%4,%5,%6,%7}, {%8,%9}, {%0,%1,%2,%3};"
        : "+f"(d[0]), "+f"(d[1]), "+f"(d[2]), "+f"(d[3])
        : "r"(a[0]), "r"(a[1]), "r"(a[2]), "r"(a[3]),
          "r"(__float_as_uint(b[0])), "r"(__float_as_uint(b[1])));
}

__device__ __forceinline__ void mma16(float* d, const uint32_t* a, const uint32_t* b) {
    asm volatile(
        "mma.sync.aligned.m16n8k16.row.col.f32.bf16.bf16.f32 "
        "{%0,%1,%2,%3}, {%4,%5,%6,%7}, {%8,%9}, {%0,%1,%2,%3};"
        : "+f"(d[0]), "+f"(d[1]), "+f"(d[2]), "+f"(d[3])
        : "r"(a[0]), "r"(a[1]), "r"(a[2]), "r"(a[3]), "r"(b[0]), "r"(b[1]));
}

// ---------------------------------------------------------------------------
// bf16 split staging (k_P / k_energy) — unchanged from R9
// ---------------------------------------------------------------------------
#define STAGE_BF2(hi, lo, v, p) do {                                          \
    const int _r = lrow + (p) * 64;                                           \
    uint32_t _h0, _h1, _l0, _l1;                                              \
    asm("cvt.rn.satfinite.bf16x2.f32 %0, %1, %2;" : "=r"(_h0)                 \
        : "f"((v).y), "f"((v).x));                                            \
    asm("cvt.rn.satfinite.bf16x2.f32 %0, %1, %2;" : "=r"(_h1)                 \
        : "f"((v).w), "f"((v).z));                                            \
    const float _hx = __uint_as_float(_h0 << 16);                             \
    const float _hy = __uint_as_float(_h0 & 0xFFFF0000u);                     \
    const float _hz = __uint_as_float(_h1 << 16);                             \
    const float _hw = __uint_as_float(_h1 & 0xFFFF0000u);                     \
    asm("cvt.rn.satfinite.bf16x2.f32 %0, %1, %2;" : "=r"(_l0)                 \
        : "f"((v).y - _hy), "f"((v).x - _hx));                                \
    asm("cvt.rn.satfinite.bf16x2.f32 %0, %1, %2;" : "=r"(_l1)                 \
        : "f"((v).w - _hw), "f"((v).z - _hz));                                \
    *(uint2*)((hi) + _r * BPITCH + (tid & 3) * 8) = make_uint2(_h0, _h1);     \
    *(uint2*)((lo) + _r * BPITCH + (tid & 3) * 8) = make_uint2(_l0, _l1);     \
} while (0)

#define COMPUTE_BF_LDSM(AHB, ALB, BHB, BLB) do {                              \
    uint32_t ah[4][4], al[4][4], bh[4][2], bl[4][2];                          \
    _Pragma("unroll")                                                         \
    for (int mi = 0; mi < 4; mi++) {                                          \
        const uint32_t _ao = aoff + mi * (16 * BPITCH);                       \
        LDSM4(ah[mi][0], ah[mi][1], ah[mi][2], ah[mi][3], (AHB) + _ao);       \
        LDSM4(al[mi][0], al[mi][1], al[mi][2], al[mi][3], (ALB) + _ao);       \
    }                                                                         \
    _Pragma("unroll")                                                         \
    for (int p = 0; p < 2; p++) {                                             \
        const uint32_t _bo = boff + p * (16 * BPITCH);                        \
        LDSM4(bh[2*p][0], bh[2*p][1], bh[2*p+1][0], bh[2*p+1][1], (BHB) + _bo); \
        LDSM4(bl[2*p][0], bl[2*p][1], bl[2*p+1][0], bl[2*p+1][1], (BLB) + _bo); \
    }                                                                         \
    _Pragma("unroll")                                                         \
    for (int mi = 0; mi < 4; mi++)                                            \
        _Pragma("unroll")                                                     \
        for (int nj = 0; nj < 4; nj++) {                                      \
            mma16(acc[mi][nj], ah[mi], bh[nj]);                               \
            mma16(acc[mi][nj], ah[mi], bl[nj]);                               \
            mma16(acc[mi][nj], al[mi], bh[nj]);                               \
        }                                                                     \
} while (0)

// ---------------------------------------------------------------------------
// tf32 cp.async compute: raw fp32 tiles in smem; RNA->tf32 applied in regs.
// A: [m][16k] fp32 pitch 80B (ldmatrix, b16 view). B: [k][n] pitch PAD floats.
// ---------------------------------------------------------------------------
#define COMPUTE_T32_ASYNC(A32B, BP)                                           \
    _Pragma("unroll")                                                         \
    for (int ks = 0; ks < 2; ks++) {                                          \
        const int k0 = ks * 8;                                                \
        uint32_t au[4][4];                                                    \
        float bf[4][2];                                                       \
        _Pragma("unroll")                                                     \
        for (int mi = 0; mi < 4; mi++) {                                      \
            const uint32_t _ao = aoff32 + mi * (16 * 80) + ks * 32;           \
            LDSM4(au[mi][0], au[mi][1], au[mi][2], au[mi][3], (A32B) + _ao);  \
            au[mi][0] = tf32u(au[mi][0]); au[mi][1] = tf32u(au[mi][1]);       \
            au[mi][2] = tf32u(au[mi][2]); au[mi][3] = tf32u(au[mi][3]);       \
        }                                                                     \
        _Pragma("unroll")                                                     \
        for (int nj = 0; nj < 4; nj++) {                                      \
            const int n = bn0 + nj * 8 + qr;                                  \
            bf[nj][0] = f2tf32((BP)[(k0 + qc) * PAD + n]);                    \
            bf[nj][1] = f2tf32((BP)[(k0 + qc + 4) * PAD + n]);                \
        }                                                                     \
        _Pragma("unroll")                                                     \
        for (int mi = 0; mi < 4; mi++)                                        \
            _Pragma("unroll")                                                 \
            for (int nj = 0; nj < 4; nj++)                                    \
                mma8u(acc[mi][nj], au[mi], bf[nj]);                           \
    }

#define WARP_IDX_SETUP                                  \
    const int tid = threadIdx.x;                        \
    const int lane = tid & 31, wid = tid >> 5;          \
    const int qr = lane >> 2, qc = lane & 3;            \
    const int am0 = (wid >> 2) * 64;                    \
    const int bn0 = (wid & 3) * 32;                     \
    const int lrow = tid >> 2, lcol = (tid & 3) * 4;    \
    (void)qr; (void)qc; (void)lrow; (void)lcol; (void)wid;

#define LDSM_A_IDX                                                            \
    const int a_row = ((lane >> 3) & 1) * 8 + (lane & 7);                     \
    const int a_kh  = ((lane >> 4) & 1) * 16;
#define LDSM_B_IDX                                                            \
    const int b_row = ((lane >> 4) & 1) * 8 + (lane & 7);                     \
    const int b_kh  = ((lane >> 3) & 1) * 16;

// Kernel c: c[m] = sum_d dec[m,d] * b_attn[d]
__global__ __launch_bounds__(256)
void k_c(const float* __restrict__ dec, const float* __restrict__ ba)
{
    const int m = blockIdx.x * 8 + (threadIdx.x >> 5);
    const int lane = threadIdx.x & 31;
    float s = 0.0f;
#pragma unroll
    for (int it = 0; it < 4; it++) {
        float4 v = *(const float4*)&dec[(size_t)m * DD + it * 128 + lane * 4];
        float4 w = *(const float4*)&ba[it * 128 + lane * 4];
        s += v.x * w.x + v.y * w.y + v.z * w.z + v.w * w.w;
    }
#pragma unroll
    for (int o = 16; o; o >>= 1) s += __shfl_xor_sync(0xffffffffu, s, o);
    if (lane == 0) g_c[m] = s;
}

// k_P (bf16-split + ldmatrix, R9 version): P[m,e] = sum_d dec[m,d]*W[e,d]
__global__ __launch_bounds__(256)
void k_P(const float* __restrict__ dec, const float* __restrict__ W)
{
    extern __shared__ char smx[];
    WARP_IDX_SETUP
    LDSM_A_IDX
    LDSM_B_IDX
    const int bm = blockIdx.y * 128, bn = blockIdx.x * 128;
    const uint32_t sb = smem_u32(smx);
    const uint32_t aoff = (am0 + a_row) * BPITCH + a_kh;
    const uint32_t boff = (bn0 + b_row) * BPITCH + b_kh;

    float4 va[2], vb[2];
#pragma unroll
    for (int p = 0; p < 2; p++) {
        va[p] = *(const float4*)&dec[(size_t)(bm + lrow + p * 64) * DD + lcol];
        vb[p] = *(const float4*)&W[(size_t)(bn + lrow + p * 64) * DD + lcol];
    }
    {
        char* b0 = smx;
        STAGE_BF2(b0, b0 + BTILE, va[0], 0); STAGE_BF2(b0, b0 + BTILE, va[1], 1);
        STAGE_BF2(b0 + 2*BTILE, b0 + 3*BTILE, vb[0], 0);
        STAGE_BF2(b0 + 2*BTILE, b0 + 3*BTILE, vb[1], 1);
    }
    __syncthreads();

    float acc[4][4][4] = {};
    const int nt = DD / 16;
    for (int t = 0; t < nt; t++) {
        const int cur = t & 1, nxt = cur ^ 1;
        const bool more = (t + 1 < nt);
        if (more) {
            const int k0 = (t + 1) * 16;
#pragma unroll
            for (int p = 0; p < 2; p++) {
                va[p] = *(const float4*)&dec[(size_t)(bm + lrow + p * 64) * DD + k0 + lcol];
                vb[p] = *(const float4*)&W[(size_t)(bn + lrow + p * 64) * DD + k0 + lcol];
            }
        }
        {
            const uint32_t s0 = sb + cur * BSTG;
            COMPUTE_BF_LDSM(s0, s0 + BTILE, s0 + 2*BTILE, s0 + 3*BTILE);
        }
        if (more) {
            char* b1 = smx + nxt * BSTG;
            STAGE_BF2(b1, b1 + BTILE, va[0], 0); STAGE_BF2(b1, b1 + BTILE, va[1], 1);
            STAGE_BF2(b1 + 2*BTILE, b1 + 3*BTILE, vb[0], 0);
            STAGE_BF2(b1 + 2*BTILE, b1 + 3*BTILE, vb[1], 1);
        }
        __syncthreads();
    }
#pragma unroll
    for (int mi = 0; mi < 4; mi++)
#pragma unroll
        for (int nj = 0; nj < 4; nj++) {
            const size_t m = bm + am0 + mi * 16 + qr;
            const int n = bn + bn0 + nj * 8 + qc * 2;
            *(float2*)&g_P[m * EE + n]       = make_float2(acc[mi][nj][0], acc[mi][nj][1]);
            *(float2*)&g_P[(m + 8) * EE + n] = make_float2(acc[mi][nj][2], acc[mi][nj][3]);
        }
}

// k_energy (bf16-split + ldmatrix, R9 version, per batch)
__global__ __launch_bounds__(256)
void k_energy(const float* __restrict__ enc, const int* __restrict__ mask,
              float* __restrict__ me)
{
    extern __shared__ char smx[];
    WARP_IDX_SETUP
    LDSM_A_IDX
    LDSM_B_IDX
    const int b = blockIdx.z;
    const int bn = blockIdx.x * 128;
    const float* A = g_P + (size_t)b * TT * EE;
    const float* Ep = enc + (size_t)b * SS * EE;
    const uint32_t sb = smem_u32(smx);
    const uint32_t aoff = (am0 + a_row) * BPITCH + a_kh;
    const uint32_t boff = (bn0 + b_row) * BPITCH + b_kh;

    float4 va[2], vb[2];
#pragma unroll
    for (int p = 0; p < 2; p++) {
        va[p] = *(const float4*)&A[(size_t)(lrow + p * 64) * EE + lcol];
        vb[p] = *(const float4*)&Ep[(size_t)(bn + lrow + p * 64) * EE + lcol];
    }
    {
        char* b0 = smx;
        STAGE_BF2(b0, b0 + BTILE, va[0], 0); STAGE_BF2(b0, b0 + BTILE, va[1], 1);
        STAGE_BF2(b0 + 2*BTILE, b0 + 3*BTILE, vb[0], 0);
        STAGE_BF2(b0 + 2*BTILE, b0 + 3*BTILE, vb[1], 1);
    }
    __syncthreads();

    float acc[4][4][4] = {};
    const int nt = EE / 16;
    for (int t = 0; t < nt; t++) {
        const int cur = t & 1, nxt = cur ^ 1;
        const bool more = (t + 1 < nt);
        if (more) {
            const int k0 = (t + 1) * 16;
#pragma unroll
            for (int p = 0; p < 2; p++) {
                va[p] = *(const float4*)&A[(size_t)(lrow + p * 64) * EE + k0 + lcol];
                vb[p] = *(const float4*)&Ep[(size_t)(bn + lrow + p * 64) * EE + k0 + lcol];
            }
        }
        {
            const uint32_t s0 = sb + cur * BSTG;
            COMPUTE_BF_LDSM(s0, s0 + BTILE, s0 + 2*BTILE, s0 + 3*BTILE);
        }
        if (more) {
            char* b1 = smx + nxt * BSTG;
            STAGE_BF2(b1, b1 + BTILE, va[0], 0); STAGE_BF2(b1, b1 + BTILE, va[1], 1);
            STAGE_BF2(b1 + 2*BTILE, b1 + 3*BTILE, vb[0], 0);
            STAGE_BF2(b1 + 2*BTILE, b1 + 3*BTILE, vb[1], 1);
        }
        __syncthreads();
    }
#pragma unroll
    for (int mi = 0; mi < 4; mi++) {
        const int t0 = am0 + mi * 16 + qr;
        const float ct0 = g_c[(size_t)b * TT + t0];
        const float ct1 = g_c[(size_t)b * TT + t0 + 8];
#pragma unroll
        for (int nj = 0; nj < 4; nj++) {
            const int s = bn + bn0 + nj * 8 + qc * 2;
            const int mk0 = mask[(size_t)b * SS + s];
            const int mk1 = mask[(size_t)b * SS + s + 1];
            float2 r0, r1;
            r0.x = mk0 ? acc[mi][nj][0] + ct0 : NEGINF;
            r0.y = mk1 ? acc[mi][nj][1] + ct0 : NEGINF;
            r1.x = mk0 ? acc[mi][nj][2] + ct1 : NEGINF;
            r1.y = mk1 ? acc[mi][nj][3] + ct1 : NEGINF;
            *(float2*)&me[((size_t)b * TT + t0) * SS + s]     = r0;
            *(float2*)&me[((size_t)b * TT + t0 + 8) * SS + s] = r1;
        }
    }
}

// Row softmax over S=512, one block (256 thr) per (b,t) row.
__global__ __launch_bounds__(256)
void k_softmax(const float* __restrict__ me, float* __restrict__ attn)
{
    const int row = blockIdx.x;
    const float* x = me + (size_t)row * SS;
    float* y = attn + (size_t)row * SS;
    const int tid = threadIdx.x;
    __shared__ float smax[8];
    __shared__ float ssum[8];

    float v0 = x[tid], v1 = x[tid + 256];
    float m = fmaxf(v0, v1);
#pragma unroll
    for (int o = 16; o; o >>= 1) m = fmaxf(m, __shfl_xor_sync(0xffffffffu, m, o));
    if ((tid & 31) == 0) smax[tid >> 5] = m;
    __syncthreads();
    float M = smax[0];
#pragma unroll
    for (int i = 1; i < 8; i++) M = fmaxf(M, smax[i]);

    float e0 = __expf(v0 - M), e1 = __expf(v1 - M);
    float s = e0 + e1;
#pragma unroll
    for (int o = 16; o; o >>= 1) s += __shfl_xor_sync(0xffffffffu, s, o);
    if ((tid & 31) == 0) ssum[tid >> 5] = s;
    __syncthreads();
    float S = 0.0f;
#pragma unroll
    for (int i = 0; i < 8; i++) S += ssum[i];
    float inv = 1.0f / S;
    y[tid] = e0 * inv;
    y[tid + 256] = e1 * inv;
}

// ---------------------------------------------------------------------------
// k_wc (tf32, 4-stage cp.async, per batch): wc[t,e] = sum_s attn[t,s]*enc[s,e]
// M=128, N=128/blk, K=512 (32 tiles).
// ---------------------------------------------------------------------------
__global__ __launch_bounds__(256)
void k_wc(const float* __restrict__ attn, const float* __restrict__ enc)
{
    extern __shared__ char smx[];
    WARP_IDX_SETUP
    LDSM_A_IDX
    const int b = blockIdx.z;
    const int bn = blockIdx.x * 128;
    const float* A = attn + (size_t)b * TT * SS;
    const float* Ep = enc + (size_t)b * SS * EE;
    const uint32_t sb = smem_u32(smx);
    const uint32_t aoff32 = (am0 + a_row) * 80 + a_kh;

    // cp.async staging indices
    const int ar = tid >> 1, aseg = tid & 1;        // A: 128 rows x 2 segs
    const int br = tid >> 4, bseg = tid & 15;       // B: 16 rows x 16 segs

#define WC_ISSUE(t_) do {                                                     \
    const int _k0 = (t_) * 16;                                                \
    const uint32_t _st = sb + ((t_) % NST) * STG32;                           \
    const char* _ga = (const char*)&A[(size_t)ar * SS + _k0] + aseg * 32;     \
    const uint32_t _sa = _st + ar * 80 + aseg * 32;                           \
    cpa16(_sa, _ga); cpa16(_sa + 16, _ga + 16);                               \
    const char* _gb = (const char*)&Ep[(size_t)(_k0 + br) * EE + bn] + bseg * 32; \
    const uint32_t _sb2 = _st + ASZ32 + br * (PAD * 4) + bseg * 32;           \
    cpa16(_sb2, _gb); cpa16(_sb2 + 16, _gb + 16);                             \
} while (0)

    const int nt = SS / 16;
#pragma unroll
    for (int s = 0; s < NST - 1; s++) { WC_ISSUE(s); CP_COMMIT(); }

    float acc[4][4][4] = {};
    for (int t = 0; t < nt; t++) {
        asm volatile("cp.async.wait_group %0;" :: "n"(NST - 2) : "memory");
        __syncthreads();
        const int tn = t + NST - 1;
        if (tn < nt) WC_ISSUE(tn);
        CP_COMMIT();
        const uint32_t st = sb + (t % NST) * STG32;
        const float* Bp = (const float*)(smx + (t % NST) * STG32 + ASZ32);
        COMPUTE_T32_ASYNC(st, Bp)
    }
#undef WC_ISSUE
#pragma unroll
    for (int mi = 0; mi < 4; mi++)
#pragma unroll
        for (int nj = 0; nj < 4; nj++) {
            const size_t m = (size_t)b * TT + am0 + mi * 16 + qr;
            const int n = bn + bn0 + nj * 8 + qc * 2;
            *(float2*)&g_wc[m * EE + n]       = make_float2(acc[mi][nj][0], acc[mi][nj][1]);
            *(float2*)&g_wc[(m + 8) * EE + n] = make_float2(acc[mi][nj][2], acc[mi][nj][3]);
        }
}

// ---------------------------------------------------------------------------
// k_out (tf32, 4-stage cp.async): ht[m,n] = tanh([wc | dec][m,:] @ W_out[:,n])
// M=8192, K=1536 (96 tiles), N=512.
// ---------------------------------------------------------------------------
__global__ __launch_bounds__(256)
void k_out(const float* __restrict__ dec, const float* __restrict__ Wout,
           float* __restrict__ ht)
{
    extern __shared__ char smx[];
    WARP_IDX_SETUP
    LDSM_A_IDX
    const int bm = blockIdx.y * 128, bn = blockIdx.x * 128;
    const uint32_t sb = smem_u32(smx);
    const uint32_t aoff32 = (am0 + a_row) * 80 + a_kh;

    const int ar = tid >> 1, aseg = tid & 1;
    const int br = tid >> 4, bseg = tid & 15;

#define OUT_ISSUE(t_) do {                                                    \
    const int _k0 = (t_) * 16;                                                \
    const uint32_t _st = sb + ((t_) % NST) * STG32;                           \
    const char* _ga;                                                          \
    if (_k0 < EE)                                                             \
        _ga = (const char*)&g_wc[(size_t)(bm + ar) * EE + _k0] + aseg * 32;   \
    else                                                                      \
        _ga = (const char*)&dec[(size_t)(bm + ar) * DD + (_k0 - EE)] + aseg * 32; \
    const uint32_t _sa = _st + ar * 80 + aseg * 32;                           \
    cpa16(_sa, _ga); cpa16(_sa + 16, _ga + 16);                               \
    const char* _gb = (const char*)&Wout[(size_t)(_k0 + br) * DD + bn] + bseg * 32; \
    const uint32_t _sb2 = _st + ASZ32 + br * (PAD * 4) + bseg * 32;           \
    cpa16(_sb2, _gb); cpa16(_sb2 + 16, _gb + 16);                             \
} while (0)

    const int nt = (EE + DD) / 16;
#pragma unroll
    for (int s = 0; s < NST - 1; s++) { OUT_ISSUE(s); CP_COMMIT(); }

    float acc[4][4][4] = {};
    for (int t = 0; t < nt; t++) {
        asm volatile("cp.async.wait_group %0;" :: "n"(NST - 2) : "memory");
        __syncthreads();
        const int tn = t + NST - 1;
        if (tn < nt) OUT_ISSUE(tn);
        CP_COMMIT();
        const uint32_t st = sb + (t % NST) * STG32;
        const float* Bp = (const float*)(smx + (t % NST) * STG32 + ASZ32);
        COMPUTE_T32_ASYNC(st, Bp)
    }
#undef OUT_ISSUE
#pragma unroll
    for (int mi = 0; mi < 4; mi++)
#pragma unroll
        for (int nj = 0; nj < 4; nj++) {
            const size_t m = bm + am0 + mi * 16 + qr;
            const int n = bn + bn0 + nj * 8 + qc * 2;
            float2 r0 = make_float2(tanhf(acc[mi][nj][0]), tanhf(acc[mi][nj][1]));
            float2 r1 = make_float2(tanhf(acc[mi][nj][2]), tanhf(acc[mi][nj][3]));
            *(float2*)&ht[m * DD + n]       = r0;
            *(float2*)&ht[(m + 8) * DD + n] = r1;
        }
}

extern "C" void kernel_launch(void* const* d_in, const int* in_sizes, int n_in,
                              void* d_out, int out_size)
{
    const float* dec    = (const float*)d_in[0];
    const float* enc    = (const float*)d_in[1];
    const int*   mask   = (const int*)d_in[2];
    const float* W_attn = (const float*)d_in[3];
    const float* b_attn = (const float*)d_in[4];
    const float* W_out  = (const float*)d_in[5];
    float* out = (float*)d_out;

    const size_t n_h    = (size_t)BB * TT * DD;
    const size_t n_attn = (size_t)BB * TT * SS;
    const size_t n_me   = (size_t)BB * TT * SS;

    float* h_tilde = out;
    float* attn;
    float* me;
    if ((size_t)out_size >= n_h + n_attn + n_me) {
        attn = out + n_h;
        me   = out + n_h + n_attn;
    } else {
        void* p;
        cudaGetSymbolAddress(&p, g_attn_scratch); attn = (float*)p;
        cudaGetSymbolAddress(&p, g_me_scratch);   me = (float*)p;
    }

    cudaFuncSetAttribute(k_P, cudaFuncAttributeMaxDynamicSharedMemorySize, SMEM_BF);
    cudaFuncSetAttribute(k_energy, cudaFuncAttributeMaxDynamicSharedMemorySize, SMEM_BF);
    cudaFuncSetAttribute(k_wc, cudaFuncAttributeMaxDynamicSharedMemorySize, SMEM32);
    cudaFuncSetAttribute(k_out, cudaFuncAttributeMaxDynamicSharedMemorySize, SMEM32);

    // 0. c = dec . b_attn
    k_c<<<dim3(BB * TT / 8), 256>>>(dec, b_attn);
    // 1. P = dec @ W_attn^T (bf16-split + ldmatrix)   M=8192 N=1024 K=512
    k_P<<<dim3(EE / 128, (BB * TT) / 128), 256, SMEM_BF>>>(dec, W_attn);
    // 2. masked energies (bf16-split + ldmatrix)      per-batch M=128 N=512 K=1024
    k_energy<<<dim3(SS / 128, 1, BB), 256, SMEM_BF>>>(enc, mask, me);
    // 3. softmax rows
    k_softmax<<<dim3(BB * TT), 256>>>(me, attn);
    // 4. weighted context (tf32, cp.async)            per-batch M=128 N=1024 K=512
    k_wc<<<dim3(EE / 128, 1, BB), 256, SMEM32>>>(attn, enc);
    // 5. h_tilde = tanh([wc, dec] @ W_out) (cp.async) M=8192 K=1536 N=512
    k_out<<<dim3(DD / 128, (BB * TT) / 128), 256, SMEM32>>>(dec, W_out, h_tilde);
}

// round 13
// speedup vs baseline: 1.2436x; 1.1978x over previous
#include <cuda_runtime.h>
#include <cstdint>

// Problem constants (fixed by dataset)
#define BB 64
#define TT 128
#define SS 512
#define EE 1024
#define DD 512
#define NEGINF (-1.0e10f)
#define PAD 132

// b16 tile geometry: [128 rows][16 k] b16, 48B row pitch (32B data + 16B pad)
#define BPITCH 48
#define BTILE  (128 * BPITCH)      // 6144 B
#define BSTG   (4 * BTILE)         // Ah, Al, Bh, Bl per stage = 24576 B
#define SMEM_BF (2 * BSTG)         // 49152 B

// Scratch (allocation-free rule: device globals)
__device__ float g_P[(size_t)BB * TT * EE];
__device__ float g_wc[(size_t)BB * TT * EE];
__device__ float g_c[(size_t)BB * TT];
__device__ float g_attn_scratch[(size_t)BB * TT * SS];
__device__ float g_me_scratch[(size_t)BB * TT * SS];

// ---------------------------------------------------------------------------
// helpers
// ---------------------------------------------------------------------------
__device__ __forceinline__ uint32_t smem_u32(const void* p) {
    uint32_t a;
    asm("{ .reg .u64 t; cvta.to.shared.u64 t, %1; cvt.u32.u64 %0, t; }"
        : "=r"(a) : "l"(p));
    return a;
}

#define LDSM4(d0, d1, d2, d3, a)                                              \
    asm volatile("ldmatrix.sync.aligned.m8n8.x4.shared.b16 {%0,%1,%2,%3}, [%4];" \
                 : "=r"(d0), "=r"(d1), "=r"(d2), "=r"(d3) : "r"(a))

// bf16 m16n8k16
__device__ __forceinline__ void mma16(float* d, const uint32_t* a, const uint32_t* b) {
    asm volatile(
        "mma.sync.aligned.m16n8k16.row.col.f32.bf16.bf16.f32 "
        "{%0,%1,%2,%3}, {%4,%5,%6,%7}, {%8,%9}, {%0,%1,%2,%3};"
        : "+f"(d[0]), "+f"(d[1]), "+f"(d[2]), "+f"(d[3])
        : "r"(a[0]), "r"(a[1]), "r"(a[2]), "r"(a[3]), "r"(b[0]), "r"(b[1]));
}

// fp16 m16n8k16 (fp32 accumulate)
__device__ __forceinline__ void mma16h(float* d, const uint32_t* a, const uint32_t* b) {
    asm volatile(
        "mma.sync.aligned.m16n8k16.row.col.f32.f16.f16.f32 "
        "{%0,%1,%2,%3}, {%4,%5,%6,%7}, {%8,%9}, {%0,%1,%2,%3};"
        : "+f"(d[0]), "+f"(d[1]), "+f"(d[2]), "+f"(d[3])
        : "r"(a[0]), "r"(a[1]), "r"(a[2]), "r"(a[3]), "r"(b[0]), "r"(b[1]));
}

// ---------------------------------------------------------------------------
// bf16 split staging (k_P / k_energy) — R9 verbatim
// ---------------------------------------------------------------------------
#define STAGE_BF2(hi, lo, v, p) do {                                          \
    const int _r = lrow + (p) * 64;                                           \
    uint32_t _h0, _h1, _l0, _l1;                                              \
    asm("cvt.rn.satfinite.bf16x2.f32 %0, %1, %2;" : "=r"(_h0)                 \
        : "f"((v).y), "f"((v).x));                                            \
    asm("cvt.rn.satfinite.bf16x2.f32 %0, %1, %2;" : "=r"(_h1)                 \
        : "f"((v).w), "f"((v).z));                                            \
    const float _hx = __uint_as_float(_h0 << 16);                             \
    const float _hy = __uint_as_float(_h0 & 0xFFFF0000u);                     \
    const float _hz = __uint_as_float(_h1 << 16);                             \
    const float _hw = __uint_as_float(_h1 & 0xFFFF0000u);                     \
    asm("cvt.rn.satfinite.bf16x2.f32 %0, %1, %2;" : "=r"(_l0)                 \
        : "f"((v).y - _hy), "f"((v).x - _hx));                                \
    asm("cvt.rn.satfinite.bf16x2.f32 %0, %1, %2;" : "=r"(_l1)                 \
        : "f"((v).w - _hw), "f"((v).z - _hz));                                \
    *(uint2*)((hi) + _r * BPITCH + (tid & 3) * 8) = make_uint2(_h0, _h1);     \
    *(uint2*)((lo) + _r * BPITCH + (tid & 3) * 8) = make_uint2(_l0, _l1);     \
} while (0)

#define COMPUTE_BF_LDSM(AHB, ALB, BHB, BLB) do {                              \
    uint32_t ah[4][4], al[4][4], bh[4][2], bl[4][2];                          \
    _Pragma("unroll")                                                         \
    for (int mi = 0; mi < 4; mi++) {                                          \
        const uint32_t _ao = aoff + mi * (16 * BPITCH);                       \
        LDSM4(ah[mi][0], ah[mi][1], ah[mi][2], ah[mi][3], (AHB) + _ao);       \
        LDSM4(al[mi][0], al[mi][1], al[mi][2], al[mi][3], (ALB) + _ao);       \
    }                                                                         \
    _Pragma("unroll")                                                         \
    for (int p = 0; p < 2; p++) {                                             \
        const uint32_t _bo = boff + p * (16 * BPITCH);                        \
        LDSM4(bh[2*p][0], bh[2*p][1], bh[2*p+1][0], bh[2*p+1][1], (BHB) + _bo); \
        LDSM4(bl[2*p][0], bl[2*p][1], bl[2*p+1][0], bl[2*p+1][1], (BLB) + _bo); \
    }                                                                         \
    _Pragma("unroll")                                                         \
    for (int mi = 0; mi < 4; mi++)                                            \
        _Pragma("unroll")                                                     \
        for (int nj = 0; nj < 4; nj++) {                                      \
            mma16(acc[mi][nj], ah[mi], bh[nj]);                               \
            mma16(acc[mi][nj], ah[mi], bl[nj]);                               \
            mma16(acc[mi][nj], al[mi], bh[nj]);                               \
        }                                                                     \
} while (0)

// ---------------------------------------------------------------------------
// fp16 staging/compute (k_wc / k_out)
// A: packed fp16 [m][k16] 48B-pitch tile (LDSM).  B: raw fp32 [k][n] pitch PAD.
// ---------------------------------------------------------------------------
#define STAGE_F16(dst, v, p) do {                                             \
    const int _r = lrow + (p) * 64;                                           \
    uint32_t _h0, _h1;                                                        \
    asm("cvt.rn.f16x2.f32 %0, %1, %2;" : "=r"(_h0) : "f"((v).y), "f"((v).x)); \
    asm("cvt.rn.f16x2.f32 %0, %1, %2;" : "=r"(_h1) : "f"((v).w), "f"((v).z)); \
    *(uint2*)((dst) + _r * BPITCH + (tid & 3) * 8) = make_uint2(_h0, _h1);    \
} while (0)

#define STAGE_RAW(H, v, p) *(float4*)&H[krow + (p) * 8][ncol] = (v)

#define COMPUTE_F16(A16B, BP) do {                                            \
    uint32_t af[4][4], bfr[4][2];                                             \
    _Pragma("unroll")                                                         \
    for (int mi = 0; mi < 4; mi++) {                                          \
        const uint32_t _ao = aoff + mi * (16 * BPITCH);                       \
        LDSM4(af[mi][0], af[mi][1], af[mi][2], af[mi][3], (A16B) + _ao);      \
    }                                                                         \
    _Pragma("unroll")                                                         \
    for (int nj = 0; nj < 4; nj++) {                                          \
        const int n = bn0 + nj * 8 + qr;                                      \
        const float x0 = (BP)[(2 * qc) * PAD + n];                            \
        const float x1 = (BP)[(2 * qc + 1) * PAD + n];                        \
        const float x2 = (BP)[(2 * qc + 8) * PAD + n];                        \
        const float x3 = (BP)[(2 * qc + 9) * PAD + n];                        \
        asm("cvt.rn.f16x2.f32 %0, %1, %2;" : "=r"(bfr[nj][0]) : "f"(x1), "f"(x0)); \
        asm("cvt.rn.f16x2.f32 %0, %1, %2;" : "=r"(bfr[nj][1]) : "f"(x3), "f"(x2)); \
    }                                                                         \
    _Pragma("unroll")                                                         \
    for (int mi = 0; mi < 4; mi++)                                            \
        _Pragma("unroll")                                                     \
        for (int nj = 0; nj < 4; nj++)                                        \
            mma16h(acc[mi][nj], af[mi], bfr[nj]);                             \
} while (0)

#define WARP_IDX_SETUP                                  \
    const int tid = threadIdx.x;                        \
    const int lane = tid & 31, wid = tid >> 5;          \
    const int qr = lane >> 2, qc = lane & 3;            \
    const int am0 = (wid >> 2) * 64;                    \
    const int bn0 = (wid & 3) * 32;                     \
    const int lrow = tid >> 2, lcol = (tid & 3) * 4;    \
    const int krow = tid >> 5, ncol = (tid & 31) * 4;   \
    (void)qr; (void)qc; (void)lrow; (void)lcol; (void)krow; (void)ncol; (void)wid;

#define LDSM_A_IDX                                                            \
    const int a_row = ((lane >> 3) & 1) * 8 + (lane & 7);                     \
    const int a_kh  = ((lane >> 4) & 1) * 16;
#define LDSM_B_IDX                                                            \
    const int b_row = ((lane >> 4) & 1) * 8 + (lane & 7);                     \
    const int b_kh  = ((lane >> 3) & 1) * 16;

// Kernel c: c[m] = sum_d dec[m,d] * b_attn[d]
__global__ __launch_bounds__(256)
void k_c(const float* __restrict__ dec, const float* __restrict__ ba)
{
    const int m = blockIdx.x * 8 + (threadIdx.x >> 5);
    const int lane = threadIdx.x & 31;
    float s = 0.0f;
#pragma unroll
    for (int it = 0; it < 4; it++) {
        float4 v = *(const float4*)&dec[(size_t)m * DD + it * 128 + lane * 4];
        float4 w = *(const float4*)&ba[it * 128 + lane * 4];
        s += v.x * w.x + v.y * w.y + v.z * w.z + v.w * w.w;
    }
#pragma unroll
    for (int o = 16; o; o >>= 1) s += __shfl_xor_sync(0xffffffffu, s, o);
    if (lane == 0) g_c[m] = s;
}

// k_P (bf16-split + ldmatrix, R9): P[m,e] = sum_d dec[m,d]*W[e,d]
__global__ __launch_bounds__(256)
void k_P(const float* __restrict__ dec, const float* __restrict__ W)
{
    extern __shared__ char smx[];
    WARP_IDX_SETUP
    LDSM_A_IDX
    LDSM_B_IDX
    const int bm = blockIdx.y * 128, bn = blockIdx.x * 128;
    const uint32_t sb = smem_u32(smx);
    const uint32_t aoff = (am0 + a_row) * BPITCH + a_kh;
    const uint32_t boff = (bn0 + b_row) * BPITCH + b_kh;

    float4 va[2], vb[2];
#pragma unroll
    for (int p = 0; p < 2; p++) {
        va[p] = *(const float4*)&dec[(size_t)(bm + lrow + p * 64) * DD + lcol];
        vb[p] = *(const float4*)&W[(size_t)(bn + lrow + p * 64) * DD + lcol];
    }
    {
        char* b0 = smx;
        STAGE_BF2(b0, b0 + BTILE, va[0], 0); STAGE_BF2(b0, b0 + BTILE, va[1], 1);
        STAGE_BF2(b0 + 2*BTILE, b0 + 3*BTILE, vb[0], 0);
        STAGE_BF2(b0 + 2*BTILE, b0 + 3*BTILE, vb[1], 1);
    }
    __syncthreads();

    float acc[4][4][4] = {};
    const int nt = DD / 16;
    for (int t = 0; t < nt; t++) {
        const int cur = t & 1, nxt = cur ^ 1;
        const bool more = (t + 1 < nt);
        if (more) {
            const int k0 = (t + 1) * 16;
#pragma unroll
            for (int p = 0; p < 2; p++) {
                va[p] = *(const float4*)&dec[(size_t)(bm + lrow + p * 64) * DD + k0 + lcol];
                vb[p] = *(const float4*)&W[(size_t)(bn + lrow + p * 64) * DD + k0 + lcol];
            }
        }
        {
            const uint32_t s0 = sb + cur * BSTG;
            COMPUTE_BF_LDSM(s0, s0 + BTILE, s0 + 2*BTILE, s0 + 3*BTILE);
        }
        if (more) {
            char* b1 = smx + nxt * BSTG;
            STAGE_BF2(b1, b1 + BTILE, va[0], 0); STAGE_BF2(b1, b1 + BTILE, va[1], 1);
            STAGE_BF2(b1 + 2*BTILE, b1 + 3*BTILE, vb[0], 0);
            STAGE_BF2(b1 + 2*BTILE, b1 + 3*BTILE, vb[1], 1);
        }
        __syncthreads();
    }
#pragma unroll
    for (int mi = 0; mi < 4; mi++)
#pragma unroll
        for (int nj = 0; nj < 4; nj++) {
            const size_t m = bm + am0 + mi * 16 + qr;
            const int n = bn + bn0 + nj * 8 + qc * 2;
            *(float2*)&g_P[m * EE + n]       = make_float2(acc[mi][nj][0], acc[mi][nj][1]);
            *(float2*)&g_P[(m + 8) * EE + n] = make_float2(acc[mi][nj][2], acc[mi][nj][3]);
        }
}

// k_energy (bf16-split + ldmatrix, R9, per batch)
__global__ __launch_bounds__(256)
void k_energy(const float* __restrict__ enc, const int* __restrict__ mask,
              float* __restrict__ me)
{
    extern __shared__ char smx[];
    WARP_IDX_SETUP
    LDSM_A_IDX
    LDSM_B_IDX
    const int b = blockIdx.z;
    const int bn = blockIdx.x * 128;
    const float* A = g_P + (size_t)b * TT * EE;
    const float* Ep = enc + (size_t)b * SS * EE;
    const uint32_t sb = smem_u32(smx);
    const uint32_t aoff = (am0 + a_row) * BPITCH + a_kh;
    const uint32_t boff = (bn0 + b_row) * BPITCH + b_kh;

    float4 va[2], vb[2];
#pragma unroll
    for (int p = 0; p < 2; p++) {
        va[p] = *(const float4*)&A[(size_t)(lrow + p * 64) * EE + lcol];
        vb[p] = *(const float4*)&Ep[(size_t)(bn + lrow + p * 64) * EE + lcol];
    }
    {
        char* b0 = smx;
        STAGE_BF2(b0, b0 + BTILE, va[0], 0); STAGE_BF2(b0, b0 + BTILE, va[1], 1);
        STAGE_BF2(b0 + 2*BTILE, b0 + 3*BTILE, vb[0], 0);
        STAGE_BF2(b0 + 2*BTILE, b0 + 3*BTILE, vb[1], 1);
    }
    __syncthreads();

    float acc[4][4][4] = {};
    const int nt = EE / 16;
    for (int t = 0; t < nt; t++) {
        const int cur = t & 1, nxt = cur ^ 1;
        const bool more = (t + 1 < nt);
        if (more) {
            const int k0 = (t + 1) * 16;
#pragma unroll
            for (int p = 0; p < 2; p++) {
                va[p] = *(const float4*)&A[(size_t)(lrow + p * 64) * EE + k0 + lcol];
                vb[p] = *(const float4*)&Ep[(size_t)(bn + lrow + p * 64) * EE + k0 + lcol];
            }
        }
        {
            const uint32_t s0 = sb + cur * BSTG;
            COMPUTE_BF_LDSM(s0, s0 + BTILE, s0 + 2*BTILE, s0 + 3*BTILE);
        }
        if (more) {
            char* b1 = smx + nxt * BSTG;
            STAGE_BF2(b1, b1 + BTILE, va[0], 0); STAGE_BF2(b1, b1 + BTILE, va[1], 1);
            STAGE_BF2(b1 + 2*BTILE, b1 + 3*BTILE, vb[0], 0);
            STAGE_BF2(b1 + 2*BTILE, b1 + 3*BTILE, vb[1], 1);
        }
        __syncthreads();
    }
#pragma unroll
    for (int mi = 0; mi < 4; mi++) {
        const int t0 = am0 + mi * 16 + qr;
        const float ct0 = g_c[(size_t)b * TT + t0];
        const float ct1 = g_c[(size_t)b * TT + t0 + 8];
#pragma unroll
        for (int nj = 0; nj < 4; nj++) {
            const int s = bn + bn0 + nj * 8 + qc * 2;
            const int mk0 = mask[(size_t)b * SS + s];
            const int mk1 = mask[(size_t)b * SS + s + 1];
            float2 r0, r1;
            r0.x = mk0 ? acc[mi][nj][0] + ct0 : NEGINF;
            r0.y = mk1 ? acc[mi][nj][1] + ct0 : NEGINF;
            r1.x = mk0 ? acc[mi][nj][2] + ct1 : NEGINF;
            r1.y = mk1 ? acc[mi][nj][3] + ct1 : NEGINF;
            *(float2*)&me[((size_t)b * TT + t0) * SS + s]     = r0;
            *(float2*)&me[((size_t)b * TT + t0 + 8) * SS + s] = r1;
        }
    }
}

// Row softmax over S=512, one block (256 thr) per (b,t) row.
__global__ __launch_bounds__(256)
void k_softmax(const float* __restrict__ me, float* __restrict__ attn)
{
    const int row = blockIdx.x;
    const float* x = me + (size_t)row * SS;
    float* y = attn + (size_t)row * SS;
    const int tid = threadIdx.x;
    __shared__ float smax[8];
    __shared__ float ssum[8];

    float v0 = x[tid], v1 = x[tid + 256];
    float m = fmaxf(v0, v1);
#pragma unroll
    for (int o = 16; o; o >>= 1) m = fmaxf(m, __shfl_xor_sync(0xffffffffu, m, o));
    if ((tid & 31) == 0) smax[tid >> 5] = m;
    __syncthreads();
    float M = smax[0];
#pragma unroll
    for (int i = 1; i < 8; i++) M = fmaxf(M, smax[i]);

    float e0 = __expf(v0 - M), e1 = __expf(v1 - M);
    float s = e0 + e1;
#pragma unroll
    for (int o = 16; o; o >>= 1) s += __shfl_xor_sync(0xffffffffu, s, o);
    if ((tid & 31) == 0) ssum[tid >> 5] = s;
    __syncthreads();
    float S = 0.0f;
#pragma unroll
    for (int i = 0; i < 8; i++) S += ssum[i];
    float inv = 1.0f / S;
    y[tid] = e0 * inv;
    y[tid + 256] = e1 * inv;
}

// k_wc (fp16 k16, double-buffered, per batch): wc[t,e] = sum_s attn[t,s]*enc[s,e]
__global__ __launch_bounds__(256)
void k_wc(const float* __restrict__ attn, const float* __restrict__ enc)
{
    __shared__ char A16[2][BTILE];
    __shared__ float Bf[2][16][PAD];
    WARP_IDX_SETUP
    LDSM_A_IDX
    const int b = blockIdx.z;
    const int bn = blockIdx.x * 128;
    const float* A = attn + (size_t)b * TT * SS;
    const float* Ep = enc + (size_t)b * SS * EE;
    const uint32_t a16b[2] = { smem_u32(A16[0]), smem_u32(A16[1]) };
    const uint32_t aoff = (am0 + a_row) * BPITCH + a_kh;

    float4 va[2], vb[2];
#pragma unroll
    for (int p = 0; p < 2; p++) {
        va[p] = *(const float4*)&A[(size_t)(lrow + p * 64) * SS + lcol];
        vb[p] = *(const float4*)&Ep[(size_t)(krow + p * 8) * EE + bn + ncol];
    }
    STAGE_F16(A16[0], va[0], 0); STAGE_F16(A16[0], va[1], 1);
    STAGE_RAW(Bf[0], vb[0], 0); STAGE_RAW(Bf[0], vb[1], 1);
    __syncthreads();

    float acc[4][4][4] = {};
    const int nt = SS / 16;
    for (int t = 0; t < nt; t++) {
        const int cur = t & 1, nxt = cur ^ 1;
        const bool more = (t + 1 < nt);
        if (more) {
            const int k0 = (t + 1) * 16;
#pragma unroll
            for (int p = 0; p < 2; p++) {
                va[p] = *(const float4*)&A[(size_t)(lrow + p * 64) * SS + k0 + lcol];
                vb[p] = *(const float4*)&Ep[(size_t)(k0 + krow + p * 8) * EE + bn + ncol];
            }
        }
        COMPUTE_F16(a16b[cur], &Bf[cur][0][0]);
        if (more) {
            STAGE_F16(A16[nxt], va[0], 0); STAGE_F16(A16[nxt], va[1], 1);
            STAGE_RAW(Bf[nxt], vb[0], 0); STAGE_RAW(Bf[nxt], vb[1], 1);
        }
        __syncthreads();
    }
#pragma unroll
    for (int mi = 0; mi < 4; mi++)
#pragma unroll
        for (int nj = 0; nj < 4; nj++) {
            const size_t m = (size_t)b * TT + am0 + mi * 16 + qr;
            const int n = bn + bn0 + nj * 8 + qc * 2;
            *(float2*)&g_wc[m * EE + n]       = make_float2(acc[mi][nj][0], acc[mi][nj][1]);
            *(float2*)&g_wc[(m + 8) * EE + n] = make_float2(acc[mi][nj][2], acc[mi][nj][3]);
        }
}

// k_out (fp16 k16, double-buffered): ht[m,n] = tanh([wc | dec][m,:] @ W_out[:,n])
__global__ __launch_bounds__(256)
void k_out(const float* __restrict__ dec, const float* __restrict__ Wout,
           float* __restrict__ ht)
{
    __shared__ char A16[2][BTILE];
    __shared__ float Bf[2][16][PAD];
    WARP_IDX_SETUP
    LDSM_A_IDX
    const int bm = blockIdx.y * 128, bn = blockIdx.x * 128;
    const uint32_t a16b[2] = { smem_u32(A16[0]), smem_u32(A16[1]) };
    const uint32_t aoff = (am0 + a_row) * BPITCH + a_kh;

    float4 va[2], vb[2];
#pragma unroll
    for (int p = 0; p < 2; p++) {
        va[p] = *(const float4*)&g_wc[(size_t)(bm + lrow + p * 64) * EE + lcol];
        vb[p] = *(const float4*)&Wout[(size_t)(krow + p * 8) * DD + bn + ncol];
    }
    STAGE_F16(A16[0], va[0], 0); STAGE_F16(A16[0], va[1], 1);
    STAGE_RAW(Bf[0], vb[0], 0); STAGE_RAW(Bf[0], vb[1], 1);
    __syncthreads();

    float acc[4][4][4] = {};
    const int nt = (EE + DD) / 16;
    for (int t = 0; t < nt; t++) {
        const int cur = t & 1, nxt = cur ^ 1;
        const bool more = (t + 1 < nt);
        if (more) {
            const int k0 = (t + 1) * 16;
#pragma unroll
            for (int p = 0; p < 2; p++) {
                if (k0 < EE)
                    va[p] = *(const float4*)&g_wc[(size_t)(bm + lrow + p * 64) * EE + k0 + lcol];
                else
                    va[p] = *(const float4*)&dec[(size_t)(bm + lrow + p * 64) * DD + (k0 - EE) + lcol];
                vb[p] = *(const float4*)&Wout[(size_t)(k0 + krow + p * 8) * DD + bn + ncol];
            }
        }
        COMPUTE_F16(a16b[cur], &Bf[cur][0][0]);
        if (more) {
            STAGE_F16(A16[nxt], va[0], 0); STAGE_F16(A16[nxt], va[1], 1);
            STAGE_RAW(Bf[nxt], vb[0], 0); STAGE_RAW(Bf[nxt], vb[1], 1);
        }
        __syncthreads();
    }
#pragma unroll
    for (int mi = 0; mi < 4; mi++)
#pragma unroll
        for (int nj = 0; nj < 4; nj++) {
            const size_t m = bm + am0 + mi * 16 + qr;
            const int n = bn + bn0 + nj * 8 + qc * 2;
            float2 r0 = make_float2(tanhf(acc[mi][nj][0]), tanhf(acc[mi][nj][1]));
            float2 r1 = make_float2(tanhf(acc[mi][nj][2]), tanhf(acc[mi][nj][3]));
            *(float2*)&ht[m * DD + n]       = r0;
            *(float2*)&ht[(m + 8) * DD + n] = r1;
        }
}

extern "C" void kernel_launch(void* const* d_in, const int* in_sizes, int n_in,
                              void* d_out, int out_size)
{
    const float* dec    = (const float*)d_in[0];
    const float* enc    = (const float*)d_in[1];
    const int*   mask   = (const int*)d_in[2];
    const float* W_attn = (const float*)d_in[3];
    const float* b_attn = (const float*)d_in[4];
    const float* W_out  = (const float*)d_in[5];
    float* out = (float*)d_out;

    const size_t n_h    = (size_t)BB * TT * DD;
    const size_t n_attn = (size_t)BB * TT * SS;
    const size_t n_me   = (size_t)BB * TT * SS;

    float* h_tilde = out;
    float* attn;
    float* me;
    if ((size_t)out_size >= n_h + n_attn + n_me) {
        attn = out + n_h;
        me   = out + n_h + n_attn;
    } else {
        void* p;
        cudaGetSymbolAddress(&p, g_attn_scratch); attn = (float*)p;
        cudaGetSymbolAddress(&p, g_me_scratch);   me = (float*)p;
    }

    cudaFuncSetAttribute(k_P, cudaFuncAttributeMaxDynamicSharedMemorySize, SMEM_BF);
    cudaFuncSetAttribute(k_energy, cudaFuncAttributeMaxDynamicSharedMemorySize, SMEM_BF);

    // 0. c = dec . b_attn
    k_c<<<dim3(BB * TT / 8), 256>>>(dec, b_attn);
    // 1. P = dec @ W_attn^T (bf16-split + ldmatrix)   M=8192 N=1024 K=512
    k_P<<<dim3(EE / 128, (BB * TT) / 128), 256, SMEM_BF>>>(dec, W_attn);
    // 2. masked energies (bf16-split + ldmatrix)      per-batch M=128 N=512 K=1024
    k_energy<<<dim3(SS / 128, 1, BB), 256, SMEM_BF>>>(enc, mask, me);
    // 3. softmax rows
    k_softmax<<<dim3(BB * TT), 256>>>(me, attn);
    // 4. weighted context (fp16 k16)                  per-batch M=128 N=1024 K=512
    k_wc<<<dim3(EE / 128, 1, BB), 256>>>(attn, enc);
    // 5. h_tilde = tanh([wc, dec] @ W_out) (fp16 k16) M=8192 K=1536 N=512
    k_out<<<dim3(DD / 128, (BB * TT) / 128), 256>>>(dec, W_out, h_tilde);
}

// round 14
// speedup vs baseline: 1.3056x; 1.0499x over previous
#include <cuda_runtime.h>
#include <cstdint>

// Problem constants (fixed by dataset)
#define BB 64
#define TT 128
#define SS 512
#define EE 1024
#define DD 512
#define NEGINF (-1.0e10f)
#define PAD 132

// b16 tile geometry: [128 rows][16 k] b16, 48B row pitch (32B data + 16B pad)
#define BPITCH 48
#define BTILE  (128 * BPITCH)      // 6144 B
#define BSTG   (4 * BTILE)         // Ah, Al, Bh, Bl per stage = 24576 B
#define SMEM_BF (2 * BSTG)         // 49152 B

// Scratch (allocation-free rule: device globals)
__device__ float g_P[(size_t)BB * TT * EE];
__device__ float g_wc[(size_t)BB * TT * EE];
__device__ float g_c[(size_t)BB * TT];
__device__ float g_attn_c[(size_t)BB * TT * SS];   // compacted attn (zero tail)
__device__ int   g_idx[(size_t)BB * SS];           // unmasked s indices (tail = 0)
__device__ int   g_cnt[BB];
__device__ float g_attn_scratch[(size_t)BB * TT * SS];
__device__ float g_me_scratch[(size_t)BB * TT * SS];

// ---------------------------------------------------------------------------
// helpers
// ---------------------------------------------------------------------------
__device__ __forceinline__ uint32_t smem_u32(const void* p) {
    uint32_t a;
    asm("{ .reg .u64 t; cvta.to.shared.u64 t, %1; cvt.u32.u64 %0, t; }"
        : "=r"(a) : "l"(p));
    return a;
}

#define LDSM4(d0, d1, d2, d3, a)                                              \
    asm volatile("ldmatrix.sync.aligned.m8n8.x4.shared.b16 {%0,%1,%2,%3}, [%4];" \
                 : "=r"(d0), "=r"(d1), "=r"(d2), "=r"(d3) : "r"(a))

// bf16 m16n8k16
__device__ __forceinline__ void mma16(float* d, const uint32_t* a, const uint32_t* b) {
    asm volatile(
        "mma.sync.aligned.m16n8k16.row.col.f32.bf16.bf16.f32 "
        "{%0,%1,%2,%3}, {%4,%5,%6,%7}, {%8,%9}, {%0,%1,%2,%3};"
        : "+f"(d[0]), "+f"(d[1]), "+f"(d[2]), "+f"(d[3])
        : "r"(a[0]), "r"(a[1]), "r"(a[2]), "r"(a[3]), "r"(b[0]), "r"(b[1]));
}

// fp16 m16n8k16 (fp32 accumulate)
__device__ __forceinline__ void mma16h(float* d, const uint32_t* a, const uint32_t* b) {
    asm volatile(
        "mma.sync.aligned.m16n8k16.row.col.f32.f16.f16.f32 "
        "{%0,%1,%2,%3}, {%4,%5,%6,%7}, {%8,%9}, {%0,%1,%2,%3};"
        : "+f"(d[0]), "+f"(d[1]), "+f"(d[2]), "+f"(d[3])
        : "r"(a[0]), "r"(a[1]), "r"(a[2]), "r"(a[3]), "r"(b[0]), "r"(b[1]));
}

// ---------------------------------------------------------------------------
// bf16 split staging (k_P / k_energy)
// ---------------------------------------------------------------------------
#define STAGE_BF2(hi, lo, v, p) do {                                          \
    const int _r = lrow + (p) * 64;                                           \
    uint32_t _h0, _h1, _l0, _l1;                                              \
    asm("cvt.rn.satfinite.bf16x2.f32 %0, %1, %2;" : "=r"(_h0)                 \
        : "f"((v).y), "f"((v).x));                                            \
    asm("cvt.rn.satfinite.bf16x2.f32 %0, %1, %2;" : "=r"(_h1)                 \
        : "f"((v).w), "f"((v).z));                                            \
    const float _hx = __uint_as_float(_h0 << 16);                             \
    const float _hy = __uint_as_float(_h0 & 0xFFFF0000u);                     \
    const float _hz = __uint_as_float(_h1 << 16);                             \
    const float _hw = __uint_as_float(_h1 & 0xFFFF0000u);                     \
    asm("cvt.rn.satfinite.bf16x2.f32 %0, %1, %2;" : "=r"(_l0)                 \
        : "f"((v).y - _hy), "f"((v).x - _hx));                                \
    asm("cvt.rn.satfinite.bf16x2.f32 %0, %1, %2;" : "=r"(_l1)                 \
        : "f"((v).w - _hw), "f"((v).z - _hz));                                \
    *(uint2*)((hi) + _r * BPITCH + (tid & 3) * 8) = make_uint2(_h0, _h1);     \
    *(uint2*)((lo) + _r * BPITCH + (tid & 3) * 8) = make_uint2(_l0, _l1);     \
} while (0)

#define COMPUTE_BF_LDSM(AHB, ALB, BHB, BLB) do {                              \
    uint32_t ah[4][4], al[4][4], bh[4][2], bl[4][2];                          \
    _Pragma("unroll")                                                         \
    for (int mi = 0; mi < 4; mi++) {                                          \
        const uint32_t _ao = aoff + mi * (16 * BPITCH);                       \
        LDSM4(ah[mi][0], ah[mi][1], ah[mi][2], ah[mi][3], (AHB) + _ao);       \
        LDSM4(al[mi][0], al[mi][1], al[mi][2], al[mi][3], (ALB) + _ao);       \
    }                                                                         \
    _Pragma("unroll")                                                         \
    for (int p = 0; p < 2; p++) {                                             \
        const uint32_t _bo = boff + p * (16 * BPITCH);                        \
        LDSM4(bh[2*p][0], bh[2*p][1], bh[2*p+1][0], bh[2*p+1][1], (BHB) + _bo); \
        LDSM4(bl[2*p][0], bl[2*p][1], bl[2*p+1][0], bl[2*p+1][1], (BLB) + _bo); \
    }                                                                         \
    _Pragma("unroll")                                                         \
    for (int mi = 0; mi < 4; mi++)                                            \
        _Pragma("unroll")                                                     \
        for (int nj = 0; nj < 4; nj++) {                                      \
            mma16(acc[mi][nj], ah[mi], bh[nj]);                               \
            mma16(acc[mi][nj], ah[mi], bl[nj]);                               \
            mma16(acc[mi][nj], al[mi], bh[nj]);                               \
        }                                                                     \
} while (0)

// ---------------------------------------------------------------------------
// fp16 staging/compute (k_wc / k_out)
// ---------------------------------------------------------------------------
#define STAGE_F16(dst, v, p) do {                                             \
    const int _r = lrow + (p) * 64;                                           \
    uint32_t _h0, _h1;                                                        \
    asm("cvt.rn.f16x2.f32 %0, %1, %2;" : "=r"(_h0) : "f"((v).y), "f"((v).x)); \
    asm("cvt.rn.f16x2.f32 %0, %1, %2;" : "=r"(_h1) : "f"((v).w), "f"((v).z)); \
    *(uint2*)((dst) + _r * BPITCH + (tid & 3) * 8) = make_uint2(_h0, _h1);    \
} while (0)

#define STAGE_RAW(H, v, p) *(float4*)&H[krow + (p) * 8][ncol] = (v)

#define COMPUTE_F16(A16B, BP) do {                                            \
    uint32_t af[4][4], bfr[4][2];                                             \
    _Pragma("unroll")                                                         \
    for (int mi = 0; mi < 4; mi++) {                                          \
        const uint32_t _ao = aoff + mi * (16 * BPITCH);                       \
        LDSM4(af[mi][0], af[mi][1], af[mi][2], af[mi][3], (A16B) + _ao);      \
    }                                                                         \
    _Pragma("unroll")                                                         \
    for (int nj = 0; nj < 4; nj++) {                                          \
        const int n = bn0 + nj * 8 + qr;                                      \
        const float x0 = (BP)[(2 * qc) * PAD + n];                            \
        const float x1 = (BP)[(2 * qc + 1) * PAD + n];                        \
        const float x2 = (BP)[(2 * qc + 8) * PAD + n];                        \
        const float x3 = (BP)[(2 * qc + 9) * PAD + n];                        \
        asm("cvt.rn.f16x2.f32 %0, %1, %2;" : "=r"(bfr[nj][0]) : "f"(x1), "f"(x0)); \
        asm("cvt.rn.f16x2.f32 %0, %1, %2;" : "=r"(bfr[nj][1]) : "f"(x3), "f"(x2)); \
    }                                                                         \
    _Pragma("unroll")                                                         \
    for (int mi = 0; mi < 4; mi++)                                            \
        _Pragma("unroll")                                                     \
        for (int nj = 0; nj < 4; nj++)                                        \
            mma16h(acc[mi][nj], af[mi], bfr[nj]);                             \
} while (0)

#define WARP_IDX_SETUP                                  \
    const int tid = threadIdx.x;                        \
    const int lane = tid & 31, wid = tid >> 5;          \
    const int qr = lane >> 2, qc = lane & 3;            \
    const int am0 = (wid >> 2) * 64;                    \
    const int bn0 = (wid & 3) * 32;                     \
    const int lrow = tid >> 2, lcol = (tid & 3) * 4;    \
    const int krow = tid >> 5, ncol = (tid & 31) * 4;   \
    (void)qr; (void)qc; (void)lrow; (void)lcol; (void)krow; (void)ncol; (void)wid;

#define LDSM_A_IDX                                                            \
    const int a_row = ((lane >> 3) & 1) * 8 + (lane & 7);                     \
    const int a_kh  = ((lane >> 4) & 1) * 16;
#define LDSM_B_IDX                                                            \
    const int b_row = ((lane >> 4) & 1) * 8 + (lane & 7);                     \
    const int b_kh  = ((lane >> 3) & 1) * 16;

// ---------------------------------------------------------------------------
// k_prep: per-batch mask compaction (prefix scan) + NEGINF-fill of me.
// ---------------------------------------------------------------------------
__global__ __launch_bounds__(256)
void k_prep(const int* __restrict__ mask, float* __restrict__ me)
{
    const int b = blockIdx.x;
    const int tid = threadIdx.x;
    const int lane = tid & 31, wid = tid >> 5;
    __shared__ int wtot[8];
    __shared__ int woff[8];
    __shared__ int s_total;

    const int f0 = mask[(size_t)b * SS + 2 * tid];
    const int f1 = mask[(size_t)b * SS + 2 * tid + 1];
    const int sum = f0 + f1;
    int x = sum;
#pragma unroll
    for (int o = 1; o < 32; o <<= 1) {
        int y = __shfl_up_sync(0xffffffffu, x, o);
        if (lane >= o) x += y;
    }
    if (lane == 31) wtot[wid] = x;
    __syncthreads();
    if (wid == 0) {
        int w = (lane < 8) ? wtot[lane] : 0;
        int xx = w;
#pragma unroll
        for (int o = 1; o < 8; o <<= 1) {
            int y = __shfl_up_sync(0xffffffffu, xx, o);
            if (lane >= o) xx += y;
        }
        if (lane < 8) woff[lane] = xx - w;
        if (lane == 7) s_total = xx;
    }
    __syncthreads();
    int off = woff[wid] + x - sum;
    if (f0) g_idx[(size_t)b * SS + off++] = 2 * tid;
    if (f1) g_idx[(size_t)b * SS + off] = 2 * tid + 1;
    const int total = s_total;
    if (tid == 0) g_cnt[b] = total;
    for (int j = total + tid; j < SS; j += 256) g_idx[(size_t)b * SS + j] = 0;

    const float4 nf = make_float4(NEGINF, NEGINF, NEGINF, NEGINF);
    float4* mp = (float4*)(me + (size_t)b * TT * SS);
#pragma unroll 4
    for (int i = tid; i < TT * SS / 4; i += 256) mp[i] = nf;
}

// Kernel c: c[m] = sum_d dec[m,d] * b_attn[d]
__global__ __launch_bounds__(256)
void k_c(const float* __restrict__ dec, const float* __restrict__ ba)
{
    const int m = blockIdx.x * 8 + (threadIdx.x >> 5);
    const int lane = threadIdx.x & 31;
    float s = 0.0f;
#pragma unroll
    for (int it = 0; it < 4; it++) {
        float4 v = *(const float4*)&dec[(size_t)m * DD + it * 128 + lane * 4];
        float4 w = *(const float4*)&ba[it * 128 + lane * 4];
        s += v.x * w.x + v.y * w.y + v.z * w.z + v.w * w.w;
    }
#pragma unroll
    for (int o = 16; o; o >>= 1) s += __shfl_xor_sync(0xffffffffu, s, o);
    if (lane == 0) g_c[m] = s;
}

// k_P (bf16-split + ldmatrix): P[m,e] = sum_d dec[m,d]*W[e,d]
__global__ __launch_bounds__(256)
void k_P(const float* __restrict__ dec, const float* __restrict__ W)
{
    extern __shared__ char smx[];
    WARP_IDX_SETUP
    LDSM_A_IDX
    LDSM_B_IDX
    const int bm = blockIdx.y * 128, bn = blockIdx.x * 128;
    const uint32_t sb = smem_u32(smx);
    const uint32_t aoff = (am0 + a_row) * BPITCH + a_kh;
    const uint32_t boff = (bn0 + b_row) * BPITCH + b_kh;

    float4 va[2], vb[2];
#pragma unroll
    for (int p = 0; p < 2; p++) {
        va[p] = *(const float4*)&dec[(size_t)(bm + lrow + p * 64) * DD + lcol];
        vb[p] = *(const float4*)&W[(size_t)(bn + lrow + p * 64) * DD + lcol];
    }
    {
        char* b0 = smx;
        STAGE_BF2(b0, b0 + BTILE, va[0], 0); STAGE_BF2(b0, b0 + BTILE, va[1], 1);
        STAGE_BF2(b0 + 2*BTILE, b0 + 3*BTILE, vb[0], 0);
        STAGE_BF2(b0 + 2*BTILE, b0 + 3*BTILE, vb[1], 1);
    }
    __syncthreads();

    float acc[4][4][4] = {};
    const int nt = DD / 16;
    for (int t = 0; t < nt; t++) {
        const int cur = t & 1, nxt = cur ^ 1;
        const bool more = (t + 1 < nt);
        if (more) {
            const int k0 = (t + 1) * 16;
#pragma unroll
            for (int p = 0; p < 2; p++) {
                va[p] = *(const float4*)&dec[(size_t)(bm + lrow + p * 64) * DD + k0 + lcol];
                vb[p] = *(const float4*)&W[(size_t)(bn + lrow + p * 64) * DD + k0 + lcol];
            }
        }
        {
            const uint32_t s0 = sb + cur * BSTG;
            COMPUTE_BF_LDSM(s0, s0 + BTILE, s0 + 2*BTILE, s0 + 3*BTILE);
        }
        if (more) {
            char* b1 = smx + nxt * BSTG;
            STAGE_BF2(b1, b1 + BTILE, va[0], 0); STAGE_BF2(b1, b1 + BTILE, va[1], 1);
            STAGE_BF2(b1 + 2*BTILE, b1 + 3*BTILE, vb[0], 0);
            STAGE_BF2(b1 + 2*BTILE, b1 + 3*BTILE, vb[1], 1);
        }
        __syncthreads();
    }
#pragma unroll
    for (int mi = 0; mi < 4; mi++)
#pragma unroll
        for (int nj = 0; nj < 4; nj++) {
            const size_t m = bm + am0 + mi * 16 + qr;
            const int n = bn + bn0 + nj * 8 + qc * 2;
            *(float2*)&g_P[m * EE + n]       = make_float2(acc[mi][nj][0], acc[mi][nj][1]);
            *(float2*)&g_P[(m + 8) * EE + n] = make_float2(acc[mi][nj][2], acc[mi][nj][3]);
        }
}

// k_energy (bf16-split, N-compacted): computes only unmasked s columns;
// scatter-stores into me (pre-filled with NEGINF by k_prep).
__global__ __launch_bounds__(256)
void k_energy(const float* __restrict__ enc, float* __restrict__ me)
{
    extern __shared__ char smx[];
    WARP_IDX_SETUP
    LDSM_A_IDX
    LDSM_B_IDX
    const int b = blockIdx.z;
    const int bn = blockIdx.x * 128;
    const int cnt_b = g_cnt[b];
    if (bn >= cnt_b) return;

    const float* A = g_P + (size_t)b * TT * EE;
    const float* Ep = enc + (size_t)b * SS * EE;
    const uint32_t sb = smem_u32(smx);
    const uint32_t aoff = (am0 + a_row) * BPITCH + a_kh;
    const uint32_t boff = (bn0 + b_row) * BPITCH + b_kh;

    // gathered B rows for this thread (fixed across k-loop; rows >= cnt give
    // garbage that is never stored)
    const int sidx0 = g_idx[(size_t)b * SS + bn + lrow];
    const int sidx1 = g_idx[(size_t)b * SS + bn + lrow + 64];

    float4 va[2], vb[2];
    va[0] = *(const float4*)&A[(size_t)lrow * EE + lcol];
    va[1] = *(const float4*)&A[(size_t)(lrow + 64) * EE + lcol];
    vb[0] = *(const float4*)&Ep[(size_t)sidx0 * EE + lcol];
    vb[1] = *(const float4*)&Ep[(size_t)sidx1 * EE + lcol];
    {
        char* b0 = smx;
        STAGE_BF2(b0, b0 + BTILE, va[0], 0); STAGE_BF2(b0, b0 + BTILE, va[1], 1);
        STAGE_BF2(b0 + 2*BTILE, b0 + 3*BTILE, vb[0], 0);
        STAGE_BF2(b0 + 2*BTILE, b0 + 3*BTILE, vb[1], 1);
    }
    __syncthreads();

    float acc[4][4][4] = {};
    const int nt = EE / 16;
    for (int t = 0; t < nt; t++) {
        const int cur = t & 1, nxt = cur ^ 1;
        const bool more = (t + 1 < nt);
        if (more) {
            const int k0 = (t + 1) * 16;
            va[0] = *(const float4*)&A[(size_t)lrow * EE + k0 + lcol];
            va[1] = *(const float4*)&A[(size_t)(lrow + 64) * EE + k0 + lcol];
            vb[0] = *(const float4*)&Ep[(size_t)sidx0 * EE + k0 + lcol];
            vb[1] = *(const float4*)&Ep[(size_t)sidx1 * EE + k0 + lcol];
        }
        {
            const uint32_t s0 = sb + cur * BSTG;
            COMPUTE_BF_LDSM(s0, s0 + BTILE, s0 + 2*BTILE, s0 + 3*BTILE);
        }
        if (more) {
            char* b1 = smx + nxt * BSTG;
            STAGE_BF2(b1, b1 + BTILE, va[0], 0); STAGE_BF2(b1, b1 + BTILE, va[1], 1);
            STAGE_BF2(b1 + 2*BTILE, b1 + 3*BTILE, vb[0], 0);
            STAGE_BF2(b1 + 2*BTILE, b1 + 3*BTILE, vb[1], 1);
        }
        __syncthreads();
    }
#pragma unroll
    for (int mi = 0; mi < 4; mi++) {
        const int t0 = am0 + mi * 16 + qr;
        const float ct0 = g_c[(size_t)b * TT + t0];
        const float ct1 = g_c[(size_t)b * TT + t0 + 8];
#pragma unroll
        for (int nj = 0; nj < 4; nj++) {
            const int j0 = bn + bn0 + nj * 8 + qc * 2;
            if (j0 < cnt_b) {
                const int s0 = g_idx[(size_t)b * SS + j0];
                me[((size_t)b * TT + t0) * SS + s0]     = acc[mi][nj][0] + ct0;
                me[((size_t)b * TT + t0 + 8) * SS + s0] = acc[mi][nj][2] + ct1;
            }
            if (j0 + 1 < cnt_b) {
                const int s1 = g_idx[(size_t)b * SS + j0 + 1];
                me[((size_t)b * TT + t0) * SS + s1]     = acc[mi][nj][1] + ct0;
                me[((size_t)b * TT + t0 + 8) * SS + s1] = acc[mi][nj][3] + ct1;
            }
        }
    }
}

// Row softmax; also emits compacted attn_c (zero tail).
__global__ __launch_bounds__(256)
void k_softmax(const float* __restrict__ me, float* __restrict__ attn)
{
    const int row = blockIdx.x;
    const int b = row >> 7;  // TT = 128
    const float* x = me + (size_t)row * SS;
    float* y = attn + (size_t)row * SS;
    const int tid = threadIdx.x;
    __shared__ float smax[8];
    __shared__ float ssum[8];
    __shared__ float s_y[SS];

    float v0 = x[tid], v1 = x[tid + 256];
    float m = fmaxf(v0, v1);
#pragma unroll
    for (int o = 16; o; o >>= 1) m = fmaxf(m, __shfl_xor_sync(0xffffffffu, m, o));
    if ((tid & 31) == 0) smax[tid >> 5] = m;
    __syncthreads();
    float M = smax[0];
#pragma unroll
    for (int i = 1; i < 8; i++) M = fmaxf(M, smax[i]);

    float e0 = __expf(v0 - M), e1 = __expf(v1 - M);
    float s = e0 + e1;
#pragma unroll
    for (int o = 16; o; o >>= 1) s += __shfl_xor_sync(0xffffffffu, s, o);
    if ((tid & 31) == 0) ssum[tid >> 5] = s;
    __syncthreads();
    float S = 0.0f;
#pragma unroll
    for (int i = 0; i < 8; i++) S += ssum[i];
    float inv = 1.0f / S;
    const float y0 = e0 * inv, y1 = e1 * inv;
    y[tid] = y0;
    y[tid + 256] = y1;
    s_y[tid] = y0;
    s_y[tid + 256] = y1;
    __syncthreads();

    const int cb = g_cnt[b];
    const int i0 = g_idx[(size_t)b * SS + tid];
    const int i1 = g_idx[(size_t)b * SS + tid + 256];
    g_attn_c[(size_t)row * SS + tid]       = (tid < cb) ? s_y[i0] : 0.0f;
    g_attn_c[(size_t)row * SS + tid + 256] = (tid + 256 < cb) ? s_y[i1] : 0.0f;
}

// k_wc (fp16 k16, k-compacted, per batch): wc[t,e] = sum_{j<cnt} attn_c[t,j]*enc[idx[j],e]
__global__ __launch_bounds__(256)
void k_wc(const float* __restrict__ enc)
{
    __shared__ char A16[2][BTILE];
    __shared__ float Bf[2][16][PAD];
    WARP_IDX_SETUP
    LDSM_A_IDX
    const int b = blockIdx.z;
    const int bn = blockIdx.x * 128;
    const int cnt_b = g_cnt[b];
    const int nk = (cnt_b + 15) >> 4;
    const float* A = g_attn_c + (size_t)b * TT * SS;
    const float* Ep = enc + (size_t)b * SS * EE;
    const int* ib = g_idx + (size_t)b * SS;
    const uint32_t a16b[2] = { smem_u32(A16[0]), smem_u32(A16[1]) };
    const uint32_t aoff = (am0 + a_row) * BPITCH + a_kh;

    float4 va[2], vb[2];
#pragma unroll
    for (int p = 0; p < 2; p++) {
        va[p] = *(const float4*)&A[(size_t)(lrow + p * 64) * SS + lcol];
        vb[p] = *(const float4*)&Ep[(size_t)ib[krow + p * 8] * EE + bn + ncol];
    }
    STAGE_F16(A16[0], va[0], 0); STAGE_F16(A16[0], va[1], 1);
    STAGE_RAW(Bf[0], vb[0], 0); STAGE_RAW(Bf[0], vb[1], 1);
    __syncthreads();

    float acc[4][4][4] = {};
    for (int t = 0; t < nk; t++) {
        const int cur = t & 1, nxt = cur ^ 1;
        const bool more = (t + 1 < nk);
        if (more) {
            const int k0 = (t + 1) * 16;
#pragma unroll
            for (int p = 0; p < 2; p++) {
                va[p] = *(const float4*)&A[(size_t)(lrow + p * 64) * SS + k0 + lcol];
                vb[p] = *(const float4*)&Ep[(size_t)ib[k0 + krow + p * 8] * EE + bn + ncol];
            }
        }
        COMPUTE_F16(a16b[cur], &Bf[cur][0][0]);
        if (more) {
            STAGE_F16(A16[nxt], va[0], 0); STAGE_F16(A16[nxt], va[1], 1);
            STAGE_RAW(Bf[nxt], vb[0], 0); STAGE_RAW(Bf[nxt], vb[1], 1);
        }
        __syncthreads();
    }
#pragma unroll
    for (int mi = 0; mi < 4; mi++)
#pragma unroll
        for (int nj = 0; nj < 4; nj++) {
            const size_t m = (size_t)b * TT + am0 + mi * 16 + qr;
            const int n = bn + bn0 + nj * 8 + qc * 2;
            *(float2*)&g_wc[m * EE + n]       = make_float2(acc[mi][nj][0], acc[mi][nj][1]);
            *(float2*)&g_wc[(m + 8) * EE + n] = make_float2(acc[mi][nj][2], acc[mi][nj][3]);
        }
}

// k_out (fp16 k16, double-buffered): ht[m,n] = tanh([wc | dec][m,:] @ W_out[:,n])
__global__ __launch_bounds__(256)
void k_out(const float* __restrict__ dec, const float* __restrict__ Wout,
           float* __restrict__ ht)
{
    __shared__ char A16[2][BTILE];
    __shared__ float Bf[2][16][PAD];
    WARP_IDX_SETUP
    LDSM_A_IDX
    const int bm = blockIdx.y * 128, bn = blockIdx.x * 128;
    const uint32_t a16b[2] = { smem_u32(A16[0]), smem_u32(A16[1]) };
    const uint32_t aoff = (am0 + a_row) * BPITCH + a_kh;

    float4 va[2], vb[2];
#pragma unroll
    for (int p = 0; p < 2; p++) {
        va[p] = *(const float4*)&g_wc[(size_t)(bm + lrow + p * 64) * EE + lcol];
        vb[p] = *(const float4*)&Wout[(size_t)(krow + p * 8) * DD + bn + ncol];
    }
    STAGE_F16(A16[0], va[0], 0); STAGE_F16(A16[0], va[1], 1);
    STAGE_RAW(Bf[0], vb[0], 0); STAGE_RAW(Bf[0], vb[1], 1);
    __syncthreads();

    float acc[4][4][4] = {};
    const int nt = (EE + DD) / 16;
    for (int t = 0; t < nt; t++) {
        const int cur = t & 1, nxt = cur ^ 1;
        const bool more = (t + 1 < nt);
        if (more) {
            const int k0 = (t + 1) * 16;
#pragma unroll
            for (int p = 0; p < 2; p++) {
                if (k0 < EE)
                    va[p] = *(const float4*)&g_wc[(size_t)(bm + lrow + p * 64) * EE + k0 + lcol];
                else
                    va[p] = *(const float4*)&dec[(size_t)(bm + lrow + p * 64) * DD + (k0 - EE) + lcol];
                vb[p] = *(const float4*)&Wout[(size_t)(k0 + krow + p * 8) * DD + bn + ncol];
            }
        }
        COMPUTE_F16(a16b[cur], &Bf[cur][0][0]);
        if (more) {
            STAGE_F16(A16[nxt], va[0], 0); STAGE_F16(A16[nxt], va[1], 1);
            STAGE_RAW(Bf[nxt], vb[0], 0); STAGE_RAW(Bf[nxt], vb[1], 1);
        }
        __syncthreads();
    }
#pragma unroll
    for (int mi = 0; mi < 4; mi++)
#pragma unroll
        for (int nj = 0; nj < 4; nj++) {
            const size_t m = bm + am0 + mi * 16 + qr;
            const int n = bn + bn0 + nj * 8 + qc * 2;
            float2 r0 = make_float2(tanhf(acc[mi][nj][0]), tanhf(acc[mi][nj][1]));
            float2 r1 = make_float2(tanhf(acc[mi][nj][2]), tanhf(acc[mi][nj][3]));
            *(float2*)&ht[m * DD + n]       = r0;
            *(float2*)&ht[(m + 8) * DD + n] = r1;
        }
}

extern "C" void kernel_launch(void* const* d_in, const int* in_sizes, int n_in,
                              void* d_out, int out_size)
{
    const float* dec    = (const float*)d_in[0];
    const float* enc    = (const float*)d_in[1];
    const int*   mask   = (const int*)d_in[2];
    const float* W_attn = (const float*)d_in[3];
    const float* b_attn = (const float*)d_in[4];
    const float* W_out  = (const float*)d_in[5];
    float* out = (float*)d_out;

    const size_t n_h    = (size_t)BB * TT * DD;
    const size_t n_attn = (size_t)BB * TT * SS;
    const size_t n_me   = (size_t)BB * TT * SS;

    float* h_tilde = out;
    float* attn;
    float* me;
    if ((size_t)out_size >= n_h + n_attn + n_me) {
        attn = out + n_h;
        me   = out + n_h + n_attn;
    } else {
        void* p;
        cudaGetSymbolAddress(&p, g_attn_scratch); attn = (float*)p;
        cudaGetSymbolAddress(&p, g_me_scratch);   me = (float*)p;
    }

    cudaFuncSetAttribute(k_P, cudaFuncAttributeMaxDynamicSharedMemorySize, SMEM_BF);
    cudaFuncSetAttribute(k_energy, cudaFuncAttributeMaxDynamicSharedMemorySize, SMEM_BF);

    // 0. mask compaction + me := NEGINF ;  c = dec . b_attn
    k_prep<<<dim3(BB), 256>>>(mask, me);
    k_c<<<dim3(BB * TT / 8), 256>>>(dec, b_attn);
    // 1. P = dec @ W_attn^T (bf16-split + ldmatrix)   M=8192 N=1024 K=512
    k_P<<<dim3(EE / 128, (BB * TT) / 128), 256, SMEM_BF>>>(dec, W_attn);
    // 2. masked energies, N-compacted (bf16-split)    per-batch M=128 N=cnt K=1024
    k_energy<<<dim3(SS / 128, 1, BB), 256, SMEM_BF>>>(enc, me);
    // 3. softmax rows (+ compacted attn_c)
    k_softmax<<<dim3(BB * TT), 256>>>(me, attn);
    // 4. weighted context, k-compacted (fp16 k16)     per-batch M=128 N=1024 K=cnt
    k_wc<<<dim3(EE / 128, 1, BB), 256>>>(enc);
    // 5. h_tilde = tanh([wc, dec] @ W_out) (fp16 k16) M=8192 K=1536 N=512
    k_out<<<dim3(DD / 128, (BB * TT) / 128), 256>>>(dec, W_out, h_tilde);
}

// round 15
// speedup vs baseline: 1.3594x; 1.0412x over previous
#include <cuda_runtime.h>
#include <cstdint>
#include <cfloat>

// Problem constants (fixed by dataset)
#define BB 64
#define TT 128
#define SS 512
#define EE 1024
#define DD 512
#define NEGINF (-1.0e10f)
#define PAD 132

// b16 tile geometry: [128 rows][16 k] b16, 48B row pitch (32B data + 16B pad)
#define BPITCH 48
#define BTILE  (128 * BPITCH)      // 6144 B
#define BSTG   (4 * BTILE)         // Ah, Al, Bh, Bl per stage = 24576 B
#define SMEM_BF (2 * BSTG)         // 49152 B

// Scratch (allocation-free rule: device globals)
__device__ float g_P[(size_t)BB * TT * EE];
__device__ float g_wc[(size_t)BB * TT * EE];
__device__ float g_c[(size_t)BB * TT];
__device__ float g_attn_c[(size_t)BB * TT * SS];     // compacted attn (zero tail)
__device__ float g_ep[2 * (size_t)BB * TT * SS];     // split-K energy partials (compacted)
__device__ int   g_idx[(size_t)BB * SS];
__device__ int   g_cnt[BB];
__device__ float g_attn_scratch[(size_t)BB * TT * SS];
__device__ float g_me_scratch[(size_t)BB * TT * SS];

// ---------------------------------------------------------------------------
// helpers
// ---------------------------------------------------------------------------
__device__ __forceinline__ uint32_t smem_u32(const void* p) {
    uint32_t a;
    asm("{ .reg .u64 t; cvta.to.shared.u64 t, %1; cvt.u32.u64 %0, t; }"
        : "=r"(a) : "l"(p));
    return a;
}

#define LDSM4(d0, d1, d2, d3, a)                                              \
    asm volatile("ldmatrix.sync.aligned.m8n8.x4.shared.b16 {%0,%1,%2,%3}, [%4];" \
                 : "=r"(d0), "=r"(d1), "=r"(d2), "=r"(d3) : "r"(a))

__device__ __forceinline__ void mma16(float* d, const uint32_t* a, const uint32_t* b) {
    asm volatile(
        "mma.sync.aligned.m16n8k16.row.col.f32.bf16.bf16.f32 "
        "{%0,%1,%2,%3}, {%4,%5,%6,%7}, {%8,%9}, {%0,%1,%2,%3};"
        : "+f"(d[0]), "+f"(d[1]), "+f"(d[2]), "+f"(d[3])
        : "r"(a[0]), "r"(a[1]), "r"(a[2]), "r"(a[3]), "r"(b[0]), "r"(b[1]));
}

__device__ __forceinline__ void mma16h(float* d, const uint32_t* a, const uint32_t* b) {
    asm volatile(
        "mma.sync.aligned.m16n8k16.row.col.f32.f16.f16.f32 "
        "{%0,%1,%2,%3}, {%4,%5,%6,%7}, {%8,%9}, {%0,%1,%2,%3};"
        : "+f"(d[0]), "+f"(d[1]), "+f"(d[2]), "+f"(d[3])
        : "r"(a[0]), "r"(a[1]), "r"(a[2]), "r"(a[3]), "r"(b[0]), "r"(b[1]));
}

// ---------------------------------------------------------------------------
// bf16 split staging (k_P / k_energy)
// ---------------------------------------------------------------------------
#define STAGE_BF2(hi, lo, v, p) do {                                          \
    const int _r = lrow + (p) * 64;                                           \
    uint32_t _h0, _h1, _l0, _l1;                                              \
    asm("cvt.rn.satfinite.bf16x2.f32 %0, %1, %2;" : "=r"(_h0)                 \
        : "f"((v).y), "f"((v).x));                                            \
    asm("cvt.rn.satfinite.bf16x2.f32 %0, %1, %2;" : "=r"(_h1)                 \
        : "f"((v).w), "f"((v).z));                                            \
    const float _hx = __uint_as_float(_h0 << 16);                             \
    const float _hy = __uint_as_float(_h0 & 0xFFFF0000u);                     \
    const float _hz = __uint_as_float(_h1 << 16);                             \
    const float _hw = __uint_as_float(_h1 & 0xFFFF0000u);                     \
    asm("cvt.rn.satfinite.bf16x2.f32 %0, %1, %2;" : "=r"(_l0)                 \
        : "f"((v).y - _hy), "f"((v).x - _hx));                                \
    asm("cvt.rn.satfinite.bf16x2.f32 %0, %1, %2;" : "=r"(_l1)                 \
        : "f"((v).w - _hw), "f"((v).z - _hz));                                \
    *(uint2*)((hi) + _r * BPITCH + (tid & 3) * 8) = make_uint2(_h0, _h1);     \
    *(uint2*)((lo) + _r * BPITCH + (tid & 3) * 8) = make_uint2(_l0, _l1);     \
} while (0)

#define COMPUTE_BF_LDSM(AHB, ALB, BHB, BLB) do {                              \
    uint32_t ah[4][4], al[4][4], bh[4][2], bl[4][2];                          \
    _Pragma("unroll")                                                         \
    for (int mi = 0; mi < 4; mi++) {                                          \
        const uint32_t _ao = aoff + mi * (16 * BPITCH);                       \
        LDSM4(ah[mi][0], ah[mi][1], ah[mi][2], ah[mi][3], (AHB) + _ao);       \
        LDSM4(al[mi][0], al[mi][1], al[mi][2], al[mi][3], (ALB) + _ao);       \
    }                                                                         \
    _Pragma("unroll")                                                         \
    for (int p = 0; p < 2; p++) {                                             \
        const uint32_t _bo = boff + p * (16 * BPITCH);                        \
        LDSM4(bh[2*p][0], bh[2*p][1], bh[2*p+1][0], bh[2*p+1][1], (BHB) + _bo); \
        LDSM4(bl[2*p][0], bl[2*p][1], bl[2*p+1][0], bl[2*p+1][1], (BLB) + _bo); \
    }                                                                         \
    _Pragma("unroll")                                                         \
    for (int mi = 0; mi < 4; mi++)                                            \
        _Pragma("unroll")                                                     \
        for (int nj = 0; nj < 4; nj++) {                                      \
            mma16(acc[mi][nj], ah[mi], bh[nj]);                               \
            mma16(acc[mi][nj], ah[mi], bl[nj]);                               \
            mma16(acc[mi][nj], al[mi], bh[nj]);                               \
        }                                                                     \
} while (0)

// ---------------------------------------------------------------------------
// fp16 staging/compute (k_wc / k_out)
// ---------------------------------------------------------------------------
#define STAGE_F16(dst, v, p) do {                                             \
    const int _r = lrow + (p) * 64;                                           \
    uint32_t _h0, _h1;                                                        \
    asm("cvt.rn.f16x2.f32 %0, %1, %2;" : "=r"(_h0) : "f"((v).y), "f"((v).x)); \
    asm("cvt.rn.f16x2.f32 %0, %1, %2;" : "=r"(_h1) : "f"((v).w), "f"((v).z)); \
    *(uint2*)((dst) + _r * BPITCH + (tid & 3) * 8) = make_uint2(_h0, _h1);    \
} while (0)

#define STAGE_RAW(H, v, p) *(float4*)&H[krow + (p) * 8][ncol] = (v)

#define COMPUTE_F16(A16B, BP) do {                                            \
    uint32_t af[4][4], bfr[4][2];                                             \
    _Pragma("unroll")                                                         \
    for (int mi = 0; mi < 4; mi++) {                                          \
        const uint32_t _ao = aoff + mi * (16 * BPITCH);                       \
        LDSM4(af[mi][0], af[mi][1], af[mi][2], af[mi][3], (A16B) + _ao);      \
    }                                                                         \
    _Pragma("unroll")                                                         \
    for (int nj = 0; nj < 4; nj++) {                                          \
        const int n = bn0 + nj * 8 + qr;                                      \
        const float x0 = (BP)[(2 * qc) * PAD + n];                            \
        const float x1 = (BP)[(2 * qc + 1) * PAD + n];                        \
        const float x2 = (BP)[(2 * qc + 8) * PAD + n];                        \
        const float x3 = (BP)[(2 * qc + 9) * PAD + n];                        \
        asm("cvt.rn.f16x2.f32 %0, %1, %2;" : "=r"(bfr[nj][0]) : "f"(x1), "f"(x0)); \
        asm("cvt.rn.f16x2.f32 %0, %1, %2;" : "=r"(bfr[nj][1]) : "f"(x3), "f"(x2)); \
    }                                                                         \
    _Pragma("unroll")                                                         \
    for (int mi = 0; mi < 4; mi++)                                            \
        _Pragma("unroll")                                                     \
        for (int nj = 0; nj < 4; nj++)                                        \
            mma16h(acc[mi][nj], af[mi], bfr[nj]);                             \
} while (0)

#define WARP_IDX_SETUP                                  \
    const int tid = threadIdx.x;                        \
    const int lane = tid & 31, wid = tid >> 5;          \
    const int qr = lane >> 2, qc = lane & 3;            \
    const int am0 = (wid >> 2) * 64;                    \
    const int bn0 = (wid & 3) * 32;                     \
    const int lrow = tid >> 2, lcol = (tid & 3) * 4;    \
    const int krow = tid >> 5, ncol = (tid & 31) * 4;   \
    (void)qr; (void)qc; (void)lrow; (void)lcol; (void)krow; (void)ncol; (void)wid;

#define LDSM_A_IDX                                                            \
    const int a_row = ((lane >> 3) & 1) * 8 + (lane & 7);                     \
    const int a_kh  = ((lane >> 4) & 1) * 16;
#define LDSM_B_IDX                                                            \
    const int b_row = ((lane >> 4) & 1) * 8 + (lane & 7);                     \
    const int b_kh  = ((lane >> 3) & 1) * 16;

// ---------------------------------------------------------------------------
// k_prep: per-batch mask compaction (prefix scan) + NEGINF-fill of me.
// ---------------------------------------------------------------------------
__global__ __launch_bounds__(256)
void k_prep(const int* __restrict__ mask, float* __restrict__ me)
{
    const int b = blockIdx.x;
    const int tid = threadIdx.x;
    const int lane = tid & 31, wid = tid >> 5;
    __shared__ int wtot[8];
    __shared__ int woff[8];
    __shared__ int s_total;

    const int f0 = mask[(size_t)b * SS + 2 * tid];
    const int f1 = mask[(size_t)b * SS + 2 * tid + 1];
    const int sum = f0 + f1;
    int x = sum;
#pragma unroll
    for (int o = 1; o < 32; o <<= 1) {
        int y = __shfl_up_sync(0xffffffffu, x, o);
        if (lane >= o) x += y;
    }
    if (lane == 31) wtot[wid] = x;
    __syncthreads();
    if (wid == 0) {
        int w = (lane < 8) ? wtot[lane] : 0;
        int xx = w;
#pragma unroll
        for (int o = 1; o < 8; o <<= 1) {
            int y = __shfl_up_sync(0xffffffffu, xx, o);
            if (lane >= o) xx += y;
        }
        if (lane < 8) woff[lane] = xx - w;
        if (lane == 7) s_total = xx;
    }
    __syncthreads();
    int off = woff[wid] + x - sum;
    if (f0) g_idx[(size_t)b * SS + off++] = 2 * tid;
    if (f1) g_idx[(size_t)b * SS + off] = 2 * tid + 1;
    const int total = s_total;
    if (tid == 0) g_cnt[b] = total;
    for (int j = total + tid; j < SS; j += 256) g_idx[(size_t)b * SS + j] = 0;

    const float4 nf = make_float4(NEGINF, NEGINF, NEGINF, NEGINF);
    float4* mp = (float4*)(me + (size_t)b * TT * SS);
#pragma unroll 4
    for (int i = tid; i < TT * SS / 4; i += 256) mp[i] = nf;
}

// Kernel c: c[m] = sum_d dec[m,d] * b_attn[d]
__global__ __launch_bounds__(256)
void k_c(const float* __restrict__ dec, const float* __restrict__ ba)
{
    const int m = blockIdx.x * 8 + (threadIdx.x >> 5);
    const int lane = threadIdx.x & 31;
    float s = 0.0f;
#pragma unroll
    for (int it = 0; it < 4; it++) {
        float4 v = *(const float4*)&dec[(size_t)m * DD + it * 128 + lane * 4];
        float4 w = *(const float4*)&ba[it * 128 + lane * 4];
        s += v.x * w.x + v.y * w.y + v.z * w.z + v.w * w.w;
    }
#pragma unroll
    for (int o = 16; o; o >>= 1) s += __shfl_xor_sync(0xffffffffu, s, o);
    if (lane == 0) g_c[m] = s;
}

// k_P (bf16-split + ldmatrix): P[m,e] = sum_d dec[m,d]*W[e,d]
__global__ __launch_bounds__(256, 2)
void k_P(const float* __restrict__ dec, const float* __restrict__ W)
{
    extern __shared__ char smx[];
    WARP_IDX_SETUP
    LDSM_A_IDX
    LDSM_B_IDX
    const int bm = blockIdx.y * 128, bn = blockIdx.x * 128;
    const uint32_t sb = smem_u32(smx);
    const uint32_t aoff = (am0 + a_row) * BPITCH + a_kh;
    const uint32_t boff = (bn0 + b_row) * BPITCH + b_kh;

    float4 va[2], vb[2];
#pragma unroll
    for (int p = 0; p < 2; p++) {
        va[p] = *(const float4*)&dec[(size_t)(bm + lrow + p * 64) * DD + lcol];
        vb[p] = *(const float4*)&W[(size_t)(bn + lrow + p * 64) * DD + lcol];
    }
    {
        char* b0 = smx;
        STAGE_BF2(b0, b0 + BTILE, va[0], 0); STAGE_BF2(b0, b0 + BTILE, va[1], 1);
        STAGE_BF2(b0 + 2*BTILE, b0 + 3*BTILE, vb[0], 0);
        STAGE_BF2(b0 + 2*BTILE, b0 + 3*BTILE, vb[1], 1);
    }
    __syncthreads();

    float acc[4][4][4] = {};
    const int nt = DD / 16;
    for (int t = 0; t < nt; t++) {
        const int cur = t & 1, nxt = cur ^ 1;
        const bool more = (t + 1 < nt);
        if (more) {
            const int k0 = (t + 1) * 16;
#pragma unroll
            for (int p = 0; p < 2; p++) {
                va[p] = *(const float4*)&dec[(size_t)(bm + lrow + p * 64) * DD + k0 + lcol];
                vb[p] = *(const float4*)&W[(size_t)(bn + lrow + p * 64) * DD + k0 + lcol];
            }
        }
        {
            const uint32_t s0 = sb + cur * BSTG;
            COMPUTE_BF_LDSM(s0, s0 + BTILE, s0 + 2*BTILE, s0 + 3*BTILE);
        }
        if (more) {
            char* b1 = smx + nxt * BSTG;
            STAGE_BF2(b1, b1 + BTILE, va[0], 0); STAGE_BF2(b1, b1 + BTILE, va[1], 1);
            STAGE_BF2(b1 + 2*BTILE, b1 + 3*BTILE, vb[0], 0);
            STAGE_BF2(b1 + 2*BTILE, b1 + 3*BTILE, vb[1], 1);
        }
        __syncthreads();
    }
#pragma unroll
    for (int mi = 0; mi < 4; mi++)
#pragma unroll
        for (int nj = 0; nj < 4; nj++) {
            const size_t m = bm + am0 + mi * 16 + qr;
            const int n = bn + bn0 + nj * 8 + qc * 2;
            *(float2*)&g_P[m * EE + n]       = make_float2(acc[mi][nj][0], acc[mi][nj][1]);
            *(float2*)&g_P[(m + 8) * EE + n] = make_float2(acc[mi][nj][2], acc[mi][nj][3]);
        }
}

// k_energy (bf16-split, N-compacted, split-K): partial energies for K-half
// kh into g_ep (compacted columns, coalesced stores).
__global__ __launch_bounds__(256, 2)
void k_energy(const float* __restrict__ enc)
{
    extern __shared__ char smx[];
    WARP_IDX_SETUP
    LDSM_A_IDX
    LDSM_B_IDX
    const int b = blockIdx.z;
    const int kh = blockIdx.y;
    const int bn = blockIdx.x * 128;
    const int cnt_b = g_cnt[b];
    if (bn >= cnt_b) return;

    const float* A = g_P + (size_t)b * TT * EE + (size_t)kh * (EE / 2);
    const float* Ep = enc + (size_t)b * SS * EE + (size_t)kh * (EE / 2);
    const uint32_t sb = smem_u32(smx);
    const uint32_t aoff = (am0 + a_row) * BPITCH + a_kh;
    const uint32_t boff = (bn0 + b_row) * BPITCH + b_kh;

    const int sidx0 = g_idx[(size_t)b * SS + bn + lrow];
    const int sidx1 = g_idx[(size_t)b * SS + bn + lrow + 64];

    float4 va[2], vb[2];
    va[0] = *(const float4*)&A[(size_t)lrow * EE + lcol];
    va[1] = *(const float4*)&A[(size_t)(lrow + 64) * EE + lcol];
    vb[0] = *(const float4*)&Ep[(size_t)sidx0 * EE + lcol];
    vb[1] = *(const float4*)&Ep[(size_t)sidx1 * EE + lcol];
    {
        char* b0 = smx;
        STAGE_BF2(b0, b0 + BTILE, va[0], 0); STAGE_BF2(b0, b0 + BTILE, va[1], 1);
        STAGE_BF2(b0 + 2*BTILE, b0 + 3*BTILE, vb[0], 0);
        STAGE_BF2(b0 + 2*BTILE, b0 + 3*BTILE, vb[1], 1);
    }
    __syncthreads();

    float acc[4][4][4] = {};
    const int nt = (EE / 2) / 16;  // 32
    for (int t = 0; t < nt; t++) {
        const int cur = t & 1, nxt = cur ^ 1;
        const bool more = (t + 1 < nt);
        if (more) {
            const int k0 = (t + 1) * 16;
            va[0] = *(const float4*)&A[(size_t)lrow * EE + k0 + lcol];
            va[1] = *(const float4*)&A[(size_t)(lrow + 64) * EE + k0 + lcol];
            vb[0] = *(const float4*)&Ep[(size_t)sidx0 * EE + k0 + lcol];
            vb[1] = *(const float4*)&Ep[(size_t)sidx1 * EE + k0 + lcol];
        }
        {
            const uint32_t s0 = sb + cur * BSTG;
            COMPUTE_BF_LDSM(s0, s0 + BTILE, s0 + 2*BTILE, s0 + 3*BTILE);
        }
        if (more) {
            char* b1 = smx + nxt * BSTG;
            STAGE_BF2(b1, b1 + BTILE, va[0], 0); STAGE_BF2(b1, b1 + BTILE, va[1], 1);
            STAGE_BF2(b1 + 2*BTILE, b1 + 3*BTILE, vb[0], 0);
            STAGE_BF2(b1 + 2*BTILE, b1 + 3*BTILE, vb[1], 1);
        }
        __syncthreads();
    }
    float* ep = g_ep + (size_t)kh * BB * TT * SS + (size_t)b * TT * SS;
#pragma unroll
    for (int mi = 0; mi < 4; mi++) {
        const int t0 = am0 + mi * 16 + qr;
#pragma unroll
        for (int nj = 0; nj < 4; nj++) {
            const int j0 = bn + bn0 + nj * 8 + qc * 2;
            *(float2*)&ep[(size_t)t0 * SS + j0]       = make_float2(acc[mi][nj][0], acc[mi][nj][1]);
            *(float2*)&ep[(size_t)(t0 + 8) * SS + j0] = make_float2(acc[mi][nj][2], acc[mi][nj][3]);
        }
    }
}

// Fused combine + softmax: e_j = ep0 + ep1 + c[t]; scatter me/attn; emit attn_c.
__global__ __launch_bounds__(256)
void k_softmax(float* __restrict__ me, float* __restrict__ attn)
{
    const int row = blockIdx.x;
    const int b = row >> 7;  // TT = 128
    const int tid = threadIdx.x;
    const int cnt_b = g_cnt[b];
    __shared__ float smax[8];
    __shared__ float ssum[8];

    float* yrow = attn + (size_t)row * SS;
    if (cnt_b == 0) {
        const float u = 1.0f / SS;
        yrow[tid] = u; yrow[tid + 256] = u;
        g_attn_c[(size_t)row * SS + tid] = 0.0f;
        g_attn_c[(size_t)row * SS + tid + 256] = 0.0f;
        return;
    }

    const float ct = g_c[row];
    const float* p0 = g_ep + (size_t)row * SS;
    const float* p1 = g_ep + (size_t)BB * TT * SS + (size_t)row * SS;
    const int j0 = tid, j1 = tid + 256;
    const float e0 = (j0 < cnt_b) ? p0[j0] + p1[j0] + ct : -FLT_MAX;
    const float e1 = (j1 < cnt_b) ? p0[j1] + p1[j1] + ct : -FLT_MAX;

    float m = fmaxf(e0, e1);
#pragma unroll
    for (int o = 16; o; o >>= 1) m = fmaxf(m, __shfl_xor_sync(0xffffffffu, m, o));
    if ((tid & 31) == 0) smax[tid >> 5] = m;
    __syncthreads();
    float M = smax[0];
#pragma unroll
    for (int i = 1; i < 8; i++) M = fmaxf(M, smax[i]);

    const float x0 = (j0 < cnt_b) ? __expf(e0 - M) : 0.0f;
    const float x1 = (j1 < cnt_b) ? __expf(e1 - M) : 0.0f;
    float s = x0 + x1;
#pragma unroll
    for (int o = 16; o; o >>= 1) s += __shfl_xor_sync(0xffffffffu, s, o);
    if ((tid & 31) == 0) ssum[tid >> 5] = s;
    __syncthreads();
    float S = 0.0f;
#pragma unroll
    for (int i = 0; i < 8; i++) S += ssum[i];
    const float inv = 1.0f / S;
    const float a0 = x0 * inv, a1 = x1 * inv;

    // zero-fill attn row (masked positions stay 0), emit compacted attn
    yrow[tid] = 0.0f; yrow[tid + 256] = 0.0f;
    g_attn_c[(size_t)row * SS + j0] = a0;
    g_attn_c[(size_t)row * SS + j1] = a1;
    __syncthreads();

    // scatter unmasked me / attn
    if (j0 < cnt_b) {
        const int s0 = g_idx[(size_t)b * SS + j0];
        me[(size_t)row * SS + s0] = e0;
        yrow[s0] = a0;
    }
    if (j1 < cnt_b) {
        const int s1 = g_idx[(size_t)b * SS + j1];
        me[(size_t)row * SS + s1] = e1;
        yrow[s1] = a1;
    }
}

// k_wc (fp16 k16, k-compacted, per batch)
__global__ __launch_bounds__(256, 2)
void k_wc(const float* __restrict__ enc)
{
    __shared__ char A16[2][BTILE];
    __shared__ float Bf[2][16][PAD];
    WARP_IDX_SETUP
    LDSM_A_IDX
    const int b = blockIdx.z;
    const int bn = blockIdx.x * 128;
    const int cnt_b = g_cnt[b];
    const int nk = (cnt_b + 15) >> 4;
    const float* A = g_attn_c + (size_t)b * TT * SS;
    const float* Ep = enc + (size_t)b * SS * EE;
    const int* ib = g_idx + (size_t)b * SS;
    const uint32_t a16b[2] = { smem_u32(A16[0]), smem_u32(A16[1]) };
    const uint32_t aoff = (am0 + a_row) * BPITCH + a_kh;

    float4 va[2], vb[2];
#pragma unroll
    for (int p = 0; p < 2; p++) {
        va[p] = *(const float4*)&A[(size_t)(lrow + p * 64) * SS + lcol];
        vb[p] = *(const float4*)&Ep[(size_t)ib[krow + p * 8] * EE + bn + ncol];
    }
    STAGE_F16(A16[0], va[0], 0); STAGE_F16(A16[0], va[1], 1);
    STAGE_RAW(Bf[0], vb[0], 0); STAGE_RAW(Bf[0], vb[1], 1);
    __syncthreads();

    float acc[4][4][4] = {};
    for (int t = 0; t < nk; t++) {
        const int cur = t & 1, nxt = cur ^ 1;
        const bool more = (t + 1 < nk);
        if (more) {
            const int k0 = (t + 1) * 16;
#pragma unroll
            for (int p = 0; p < 2; p++) {
                va[p] = *(const float4*)&A[(size_t)(lrow + p * 64) * SS + k0 + lcol];
                vb[p] = *(const float4*)&Ep[(size_t)ib[k0 + krow + p * 8] * EE + bn + ncol];
            }
        }
        COMPUTE_F16(a16b[cur], &Bf[cur][0][0]);
        if (more) {
            STAGE_F16(A16[nxt], va[0], 0); STAGE_F16(A16[nxt], va[1], 1);
            STAGE_RAW(Bf[nxt], vb[0], 0); STAGE_RAW(Bf[nxt], vb[1], 1);
        }
        __syncthreads();
    }
#pragma unroll
    for (int mi = 0; mi < 4; mi++)
#pragma unroll
        for (int nj = 0; nj < 4; nj++) {
            const size_t m = (size_t)b * TT + am0 + mi * 16 + qr;
            const int n = bn + bn0 + nj * 8 + qc * 2;
            *(float2*)&g_wc[m * EE + n]       = make_float2(acc[mi][nj][0], acc[mi][nj][1]);
            *(float2*)&g_wc[(m + 8) * EE + n] = make_float2(acc[mi][nj][2], acc[mi][nj][3]);
        }
}

// k_out (fp16 k16): ht[m,n] = tanh([wc | dec][m,:] @ W_out[:,n])
__global__ __launch_bounds__(256, 2)
void k_out(const float* __restrict__ dec, const float* __restrict__ Wout,
           float* __restrict__ ht)
{
    __shared__ char A16[2][BTILE];
    __shared__ float Bf[2][16][PAD];
    WARP_IDX_SETUP
    LDSM_A_IDX
    const int bm = blockIdx.y * 128, bn = blockIdx.x * 128;
    const uint32_t a16b[2] = { smem_u32(A16[0]), smem_u32(A16[1]) };
    const uint32_t aoff = (am0 + a_row) * BPITCH + a_kh;

    float4 va[2], vb[2];
#pragma unroll
    for (int p = 0; p < 2; p++) {
        va[p] = *(const float4*)&g_wc[(size_t)(bm + lrow + p * 64) * EE + lcol];
        vb[p] = *(const float4*)&Wout[(size_t)(krow + p * 8) * DD + bn + ncol];
    }
    STAGE_F16(A16[0], va[0], 0); STAGE_F16(A16[0], va[1], 1);
    STAGE_RAW(Bf[0], vb[0], 0); STAGE_RAW(Bf[0], vb[1], 1);
    __syncthreads();

    float acc[4][4][4] = {};
    const int nt = (EE + DD) / 16;
    for (int t = 0; t < nt; t++) {
        const int cur = t & 1, nxt = cur ^ 1;
        const bool more = (t + 1 < nt);
        if (more) {
            const int k0 = (t + 1) * 16;
#pragma unroll
            for (int p = 0; p < 2; p++) {
                if (k0 < EE)
                    va[p] = *(const float4*)&g_wc[(size_t)(bm + lrow + p * 64) * EE + k0 + lcol];
                else
                    va[p] = *(const float4*)&dec[(size_t)(bm + lrow + p * 64) * DD + (k0 - EE) + lcol];
                vb[p] = *(const float4*)&Wout[(size_t)(k0 + krow + p * 8) * DD + bn + ncol];
            }
        }
        COMPUTE_F16(a16b[cur], &Bf[cur][0][0]);
        if (more) {
            STAGE_F16(A16[nxt], va[0], 0); STAGE_F16(A16[nxt], va[1], 1);
            STAGE_RAW(Bf[nxt], vb[0], 0); STAGE_RAW(Bf[nxt], vb[1], 1);
        }
        __syncthreads();
    }
#pragma unroll
    for (int mi = 0; mi < 4; mi++)
#pragma unroll
        for (int nj = 0; nj < 4; nj++) {
            const size_t m = bm + am0 + mi * 16 + qr;
            const int n = bn + bn0 + nj * 8 + qc * 2;
            float2 r0 = make_float2(tanhf(acc[mi][nj][0]), tanhf(acc[mi][nj][1]));
            float2 r1 = make_float2(tanhf(acc[mi][nj][2]), tanhf(acc[mi][nj][3]));
            *(float2*)&ht[m * DD + n]       = r0;
            *(float2*)&ht[(m + 8) * DD + n] = r1;
        }
}

extern "C" void kernel_launch(void* const* d_in, const int* in_sizes, int n_in,
                              void* d_out, int out_size)
{
    const float* dec    = (const float*)d_in[0];
    const float* enc    = (const float*)d_in[1];
    const int*   mask   = (const int*)d_in[2];
    const float* W_attn = (const float*)d_in[3];
    const float* b_attn = (const float*)d_in[4];
    const float* W_out  = (const float*)d_in[5];
    float* out = (float*)d_out;

    const size_t n_h    = (size_t)BB * TT * DD;
    const size_t n_attn = (size_t)BB * TT * SS;
    const size_t n_me   = (size_t)BB * TT * SS;

    float* h_tilde = out;
    float* attn;
    float* me;
    if ((size_t)out_size >= n_h + n_attn + n_me) {
        attn = out + n_h;
        me   = out + n_h + n_attn;
    } else {
        void* p;
        cudaGetSymbolAddress(&p, g_attn_scratch); attn = (float*)p;
        cudaGetSymbolAddress(&p, g_me_scratch);   me = (float*)p;
    }

    cudaFuncSetAttribute(k_P, cudaFuncAttributeMaxDynamicSharedMemorySize, SMEM_BF);
    cudaFuncSetAttribute(k_energy, cudaFuncAttributeMaxDynamicSharedMemorySize, SMEM_BF);

    // 0. mask compaction + me := NEGINF ;  c = dec . b_attn
    k_prep<<<dim3(BB), 256>>>(mask, me);
    k_c<<<dim3(BB * TT / 8), 256>>>(dec, b_attn);
    // 1. P = dec @ W_attn^T (bf16-split + ldmatrix)   M=8192 N=1024 K=512
    k_P<<<dim3(EE / 128, (BB * TT) / 128), 256, SMEM_BF>>>(dec, W_attn);
    // 2. energy partials, N-compacted + split-K=2     per-batch M=128 N=cnt K=512 each
    k_energy<<<dim3(SS / 128, 2, BB), 256, SMEM_BF>>>(enc);
    // 3. fused combine + softmax (+ me/attn scatter, compacted attn_c)
    k_softmax<<<dim3(BB * TT), 256>>>(me, attn);
    // 4. weighted context, k-compacted (fp16 k16)     per-batch M=128 N=1024 K=cnt
    k_wc<<<dim3(EE / 128, 1, BB), 256>>>(enc);
    // 5. h_tilde = tanh([wc, dec] @ W_out) (fp16 k16) M=8192 K=1536 N=512
    k_out<<<dim3(DD / 128, (BB * TT) / 128), 256>>>(dec, W_out, h_tilde);
}